// round 10
// baseline (speedup 1.0000x reference)
#include <cuda_runtime.h>
#include <cuda_fp16.h>
#include <math.h>
#include <stdint.h>

// ---------------------------------------------------------------------------
// Swin block: fp16 HMMA GEMMs. K=192 GEMMs use a B-resident multi-M-tile
// pipeline (T=8 tiles/CTA); fc2 (K=768) streams. Tensorized attention.
// ---------------------------------------------------------------------------

#define BATCH   64
#define HH      56
#define WW_     56
#define CC      192
#define WS_     7
#define SS_     3
#define NH_     6
#define HD_     32
#define NTOK    49
#define NWIN    4096
#define MROWS   200704
#define HIDDEN  768
#define EPS_    1e-5f

// ------------------------------- scratch -----------------------------------
__device__ __half g_ln  [(size_t)MROWS * 192];
__device__ __half g_attn[(size_t)MROWS * 192];
__device__ __half g_hid [(size_t)MROWS * 768];
__device__ __half g_qkv [(size_t)MROWS * 576];
__device__ float g_xnew[(size_t)MROWS * CC];
__device__ __half g_wqkv [640 * 192];
__device__ __half g_wproj[256 * 192];
__device__ __half g_wfc1 [768 * 192];
__device__ __half g_wfc2 [256 * 768];

// ------------------------------ helpers -------------------------------------
__device__ __forceinline__ uint32_t smem_u32(const void* p) {
    uint32_t a;
    asm("{ .reg .u64 t; cvta.to.shared.u64 t, %1; cvt.u32.u64 %0, t; }"
        : "=r"(a) : "l"(p));
    return a;
}
#define SWZ(o) ((o) ^ (((o) >> 3) & 0x70))

__device__ __forceinline__ void cp16(uint32_t dst, const void* src) {
    asm volatile("cp.async.cg.shared.global [%0], [%1], 16;"
                 :: "r"(dst), "l"(src));
}
__device__ __forceinline__ void cp_commit() {
    asm volatile("cp.async.commit_group;" ::: "memory");
}
__device__ __forceinline__ void cp_wait1() {
    asm volatile("cp.async.wait_group 1;" ::: "memory");
}
__device__ __forceinline__ void ldm4(uint32_t* r, uint32_t addr) {
    asm volatile("ldmatrix.sync.aligned.m8n8.x4.shared.b16 {%0,%1,%2,%3}, [%4];"
                 : "=r"(r[0]), "=r"(r[1]), "=r"(r[2]), "=r"(r[3]) : "r"(addr));
}
__device__ __forceinline__ void mma16816(float* c, const uint32_t* a,
                                         uint32_t b0, uint32_t b1) {
    asm volatile(
        "mma.sync.aligned.m16n8k16.row.col.f32.f16.f16.f32 "
        "{%0,%1,%2,%3}, {%4,%5,%6,%7}, {%8,%9}, {%0,%1,%2,%3};"
        : "+f"(c[0]), "+f"(c[1]), "+f"(c[2]), "+f"(c[3])
        : "r"(a[0]), "r"(a[1]), "r"(a[2]), "r"(a[3]), "r"(b0), "r"(b1));
}
__device__ __forceinline__ uint32_t h2u(__half2 v) { return *(uint32_t*)&v; }

__device__ __forceinline__ int rowmap_of(int m) {
    int bwin = m / NTOK, tok = m - bwin * NTOK;
    int b = bwin >> 6, w = bwin & 63;
    int wh = w >> 3, ww = w & 7;
    int r = tok / WS_, c = tok - r * WS_;
    int oh = wh * WS_ + r + SS_; if (oh >= HH)  oh -= HH;
    int ow = ww * WS_ + c + SS_; if (ow >= WW_) ow -= WW_;
    return b * (HH * WW_) + oh * WW_ + ow;
}

// -------------------------- small prep kernels ------------------------------
__global__ void whalf_kernel(const float* __restrict__ W,
                             __half* __restrict__ out, int Kd, int Nd, int NP) {
    int idx = blockIdx.x * 256 + threadIdx.x;
    if (idx >= NP * Kd) return;
    int n = idx / Kd, k = idx - n * Kd;
    out[idx] = (n < Nd) ? __float2half(W[(size_t)k * Nd + n]) : __half(0);
}

__global__ void ln_kernel(const float* __restrict__ in,
                          const float* __restrict__ w,
                          const float* __restrict__ b,
                          __half* __restrict__ out) {
    int row  = blockIdx.x * 8 + (threadIdx.x >> 5);
    int lane = threadIdx.x & 31;
    const float* p = in + (size_t)row * CC;
    float v[6];
    float s = 0.f;
#pragma unroll
    for (int i = 0; i < 6; i++) { v[i] = p[lane + 32 * i]; s += v[i]; }
#pragma unroll
    for (int o = 16; o > 0; o >>= 1) s += __shfl_xor_sync(0xffffffffu, s, o);
    float mean = s * (1.f / CC);
    float q = 0.f;
#pragma unroll
    for (int i = 0; i < 6; i++) { float d = v[i] - mean; q += d * d; }
#pragma unroll
    for (int o = 16; o > 0; o >>= 1) q += __shfl_xor_sync(0xffffffffu, q, o);
    float inv = rsqrtf(q * (1.f / CC) + EPS_);
    __half* op = out + (size_t)row * CC;
#pragma unroll
    for (int i = 0; i < 6; i++) {
        int c = lane + 32 * i;
        op[c] = __float2half((v[i] - mean) * inv * w[c] + b[c]);
    }
}

// ------------------- B-resident GEMM (K=192, T M-tiles/CTA) ------------------
// smem: B 3 chunks x 16KB (48KB) | A 3 stages x 16KB (48KB) = 96KB.
// MODE 0: QKV gather->g_qkv, MODE 1: proj scatter+shortcut->g_xnew,
// MODE 2: fc1+GELU->g_hid.
#define TTILES 8
template<int MODE, int NREAL>
__global__ __launch_bounds__(256, 2)
void bres_gemm(const __half* __restrict__ A,
               const __half* __restrict__ Bhi,
               const float* __restrict__ bias,
               const float* __restrict__ aux)
{
    extern __shared__ __align__(128) char dynsm[];
    constexpr int K = 192;
    constexpr int NITER = 3 * TTILES;

    const int tid  = threadIdx.x;
    const int lane = tid & 31;
    const int warp = tid >> 5;
    const int wm = warp & 3;
    const int wn = warp >> 2;
    const int blockN  = blockIdx.x * 128;
    const int blockM0 = blockIdx.y * (TTILES * 128);
    const uint32_t sbB = smem_u32(dynsm);          // B: 3 x 16KB
    const uint32_t sbA = sbB + 49152;              // A stages: 3 x 16KB

    // ---- load B once (12 cp16/thread) ----
#pragma unroll
    for (int i = 0; i < 12; i++) {
        int idx = i * 256 + tid;
        int chunk = idx >> 10, rem = idx & 1023;
        int n = rem >> 3, u = rem & 7;
        cp16(sbB + chunk * 16384 + SWZ((uint32_t)(n * 128 + u * 16)),
             Bhi + (size_t)(blockN + n) * K + chunk * 64 + u * 8);
    }

    // A per-thread load pattern (row/col within tile)
    int aRow[4];
    uint32_t aDst[4];
#pragma unroll
    for (int i = 0; i < 4; i++) {
        int idx = i * 256 + tid;
        aRow[i] = idx >> 3;
        int u = idx & 7;
        aDst[i] = SWZ((uint32_t)(aRow[i] * 128 + u * 16));
    }
    const int aCol = (tid & 7) * 8;

    auto issueA = [&](int tc) {
        int t = tc / 3, c = tc - t * 3;
        const uint32_t sb = sbA + (tc % 3) * 16384;
        int mbase = blockM0 + t * 128;
#pragma unroll
        for (int i = 0; i < 4; i++) {
            int m = mbase + aRow[i];
            int gm = (MODE == 0) ? rowmap_of(m) : m;
            cp16(sb + aDst[i], A + (size_t)gm * K + c * 64 + aCol);
        }
    };

    uint32_t oA[2], oB[4];
#pragma unroll
    for (int tm = 0; tm < 2; tm++)
        oA[tm] = (uint32_t)((wm * 32 + tm * 16 + (lane & 15)) * 128 + (lane >> 4) * 16);
#pragma unroll
    for (int g = 0; g < 4; g++)
        oB[g] = (uint32_t)((wn * 64 + g * 16 + (lane & 7) + ((lane >> 4) & 1) * 8) * 128
                           + ((lane >> 3) & 1) * 16);

    float Cr[2][8][4];
#pragma unroll
    for (int a = 0; a < 2; a++)
#pragma unroll
        for (int b = 0; b < 8; b++)
#pragma unroll
            for (int c = 0; c < 4; c++) Cr[a][b][c] = 0.f;

    issueA(0); cp_commit();        // group0: B + A0
    issueA(1); cp_commit();        // group1: A1

    const int r0l = wm * 32 + (lane >> 2);
    const int n0 = blockN + wn * 64 + 2 * (lane & 3);

    for (int tc = 0; tc < NITER; tc++) {
        const int c = tc % 3;
        cp_wait1();
        __syncthreads();
        if (tc + 2 < NITER) { issueA(tc + 2); cp_commit(); }

        const uint32_t aB = sbA + (tc % 3) * 16384;
        const uint32_t bB = sbB + c * 16384;
#pragma unroll
        for (int k16 = 0; k16 < 4; k16++) {
            const uint32_t ko = k16 * 32;
            uint32_t Ah[2][4], Bh[4][4];
#pragma unroll
            for (int tm = 0; tm < 2; tm++)
                ldm4(Ah[tm], aB + SWZ(oA[tm] + ko));
#pragma unroll
            for (int g = 0; g < 4; g++)
                ldm4(Bh[g], bB + SWZ(oB[g] + ko));
#pragma unroll
            for (int tm = 0; tm < 2; tm++)
#pragma unroll
                for (int tn = 0; tn < 8; tn++)
                    mma16816(Cr[tm][tn], Ah[tm],
                             Bh[tn >> 1][(tn & 1) * 2], Bh[tn >> 1][(tn & 1) * 2 + 1]);
        }

        if (c == 2) {
            // ---------------- epilogue for tile t ----------------
            const int mb = blockM0 + (tc / 3) * 128;
#pragma unroll
            for (int tm = 0; tm < 2; tm++) {
#pragma unroll
                for (int tn = 0; tn < 8; tn++) {
                    int n = n0 + tn * 8;
                    if (n >= NREAL) continue;
                    float bx = bias[n], by = bias[n + 1];
#pragma unroll
                    for (int half_ = 0; half_ < 2; half_++) {
                        int m = mb + r0l + tm * 16 + half_ * 8;
                        float vx = Cr[tm][tn][half_ * 2 + 0] + bx;
                        float vy = Cr[tm][tn][half_ * 2 + 1] + by;
                        if (MODE == 0) {
                            *(__half2*)(g_qkv + (size_t)m * 576 + n) =
                                __floats2half2_rn(vx, vy);
                        } else if (MODE == 1) {
                            size_t idx = (size_t)rowmap_of(m) * CC + n;
                            float2 a = *(const float2*)(aux + idx);
                            *(float2*)(g_xnew + idx) = make_float2(vx + a.x, vy + a.y);
                        } else {
                            vx = 0.5f * vx * (1.f + erff(vx * 0.70710678118654752f));
                            vy = 0.5f * vy * (1.f + erff(vy * 0.70710678118654752f));
                            *(__half2*)(g_hid + (size_t)m * HIDDEN + n) =
                                __floats2half2_rn(vx, vy);
                        }
                    }
                }
            }
#pragma unroll
            for (int a = 0; a < 2; a++)
#pragma unroll
                for (int b = 0; b < 8; b++)
#pragma unroll
                    for (int cc2 = 0; cc2 < 4; cc2++) Cr[a][b][cc2] = 0.f;
        }
    }
}

// --------------------- streaming GEMM (fc2, K=768) ---------------------------
#define STAGE_B 32768
template<int K, int NREAL>
__global__ __launch_bounds__(256, 2)
void mma_gemm_fc2(const __half* __restrict__ A,
                  const __half* __restrict__ Bhi,
                  const float* __restrict__ bias,
                  float* __restrict__ outp)
{
    extern __shared__ __align__(128) char dynsm[];
    constexpr int NCH = K / 64;

    const int tid  = threadIdx.x;
    const int lane = tid & 31;
    const int warp = tid >> 5;
    const int wm = warp & 3;
    const int wn = warp >> 2;
    const int blockN = blockIdx.x * 128;
    const int blockM = blockIdx.y * 128;
    const uint32_t sb0 = smem_u32(dynsm);

    const __half* aSrc[4];
    uint32_t aDst[4];
#pragma unroll
    for (int i = 0; i < 4; i++) {
        int idx = i * 256 + tid;
        int row = idx >> 3, u = idx & 7;
        aSrc[i] = A + (size_t)(blockM + row) * K + u * 8;
        aDst[i] = SWZ((uint32_t)(row * 128 + u * 16));
    }
    const __half* bSrc[4];
    uint32_t bDst[4];
#pragma unroll
    for (int i = 0; i < 4; i++) {
        int idx = i * 256 + tid;
        int n = idx >> 3, u = idx & 7;
        bSrc[i] = Bhi + (size_t)(blockN + n) * K + u * 8;
        bDst[i] = SWZ((uint32_t)(n * 128 + u * 16));
    }

    auto issue = [&](int c, int st) {
        const uint32_t sb = sb0 + st * STAGE_B;
#pragma unroll
        for (int i = 0; i < 4; i++)
            cp16(sb + aDst[i], aSrc[i] + c * 64);
#pragma unroll
        for (int i = 0; i < 4; i++)
            cp16(sb + 16384 + bDst[i], bSrc[i] + c * 64);
    };

    uint32_t oA[2], oB[4];
#pragma unroll
    for (int tm = 0; tm < 2; tm++)
        oA[tm] = (uint32_t)((wm * 32 + tm * 16 + (lane & 15)) * 128 + (lane >> 4) * 16);
#pragma unroll
    for (int g = 0; g < 4; g++)
        oB[g] = (uint32_t)((wn * 64 + g * 16 + (lane & 7) + ((lane >> 4) & 1) * 8) * 128
                           + ((lane >> 3) & 1) * 16);

    float Cr[2][8][4];
#pragma unroll
    for (int a = 0; a < 2; a++)
#pragma unroll
        for (int b = 0; b < 8; b++)
#pragma unroll
            for (int c = 0; c < 4; c++) Cr[a][b][c] = 0.f;

    issue(0, 0); cp_commit();
    issue(1, 1); cp_commit();

    for (int c = 0; c < NCH; c++) {
        const int st = c % 3;
        cp_wait1();
        __syncthreads();
        if (c + 2 < NCH) { issue(c + 2, (c + 2) % 3); cp_commit(); }

        const uint32_t aB = sb0 + st * STAGE_B;
        const uint32_t bB = aB + 16384;
#pragma unroll
        for (int k16 = 0; k16 < 4; k16++) {
            const uint32_t ko = k16 * 32;
            uint32_t Ah[2][4], Bh[4][4];
#pragma unroll
            for (int tm = 0; tm < 2; tm++)
                ldm4(Ah[tm], aB + SWZ(oA[tm] + ko));
#pragma unroll
            for (int g = 0; g < 4; g++)
                ldm4(Bh[g], bB + SWZ(oB[g] + ko));
#pragma unroll
            for (int tm = 0; tm < 2; tm++)
#pragma unroll
                for (int tn = 0; tn < 8; tn++)
                    mma16816(Cr[tm][tn], Ah[tm],
                             Bh[tn >> 1][(tn & 1) * 2], Bh[tn >> 1][(tn & 1) * 2 + 1]);
        }
    }

    const int r0 = blockM + wm * 32 + (lane >> 2);
    const int n0 = blockN + wn * 64 + 2 * (lane & 3);
#pragma unroll
    for (int tm = 0; tm < 2; tm++) {
#pragma unroll
        for (int tn = 0; tn < 8; tn++) {
            int n = n0 + tn * 8;
            if (n >= NREAL) continue;
            float bx = bias[n], by = bias[n + 1];
#pragma unroll
            for (int half_ = 0; half_ < 2; half_++) {
                int m = r0 + tm * 16 + half_ * 8;
                size_t idx = (size_t)m * CC + n;
                float2 a = *(const float2*)(g_xnew + idx);
                *(float2*)(outp + idx) =
                    make_float2(Cr[tm][tn][half_ * 2 + 0] + bx + a.x,
                                Cr[tm][tn][half_ * 2 + 1] + by + a.y);
            }
        }
    }
}

// ------------------------------ attention (HMMA) -----------------------------
__global__ __launch_bounds__(256)
void attn_kernel(const float* __restrict__ rpb) {
    __shared__ __align__(16) __half sq [2][64 * 40];
    __shared__ __align__(16) __half skk[2][64 * 40];
    __shared__ __align__(16) __half svt[2][32 * 72];
    __shared__ float srpb[6 * 169];
    __shared__ int   slabel[64];

    const int bwin = blockIdx.x;
    const int tid  = threadIdx.x;
    const int lane = tid & 31;
    const int warp = tid >> 5;
    const int hw = warp >> 2;
    const int mb = warp & 3;
    const float scale = 0.17677669529663687f;

    for (int idx = tid; idx < 6 * 169; idx += 256)
        srpb[idx] = rpb[(idx % 169) * NH_ + idx / 169];
    if (tid < 64) {
        int label = 0;
        if (tid < NTOK) {
            int w = bwin & 63;
            int wh = w >> 3, ww = w & 7;
            int r = tid / WS_, c = tid - r * WS_;
            int gh = wh * WS_ + r, gw = ww * WS_ + c;
            int rr = (gh < HH - WS_) ? 0 : (gh < HH - SS_) ? 1 : 2;
            int cc = (gw < WW_ - WS_) ? 0 : (gw < WW_ - SS_) ? 1 : 2;
            label = rr * 3 + cc;
        }
        slabel[tid] = label;
    }

    const int i0 = mb * 16 + (lane >> 2);
    const int i1 = i0 + 8;
    const int ri0 = i0 / WS_, ci0 = i0 - ri0 * WS_;
    const int ri1 = i1 / WS_, ci1 = i1 - ri1 * WS_;

    for (int p = 0; p < 3; p++) {
        __syncthreads();
        for (int t = tid; t < (2 * 32 * 72) / 2; t += 256)
            ((uint32_t*)svt)[t] = 0;
        __syncthreads();
        for (int idx = tid; idx < 2 * NTOK * 16; idx += 256) {
            int h = (idx >= NTOK * 16);
            int rem = idx - h * NTOK * 16;
            int tok = rem >> 4, d2 = (rem & 15) * 2;
            const __half* src = g_qkv + (size_t)(bwin * NTOK + tok) * 576
                                + (p * 2 + h) * 32 + d2;
            float2 qf = __half22float2(*(const __half2*)src);
            *(__half2*)(&sq[h][tok * 40 + d2]) = __floats2half2_rn(qf.x * scale, qf.y * scale);
            *(__half2*)(&skk[h][tok * 40 + d2]) = *(const __half2*)(src + 192);
            __half2 vv = *(const __half2*)(src + 384);
            svt[h][d2 * 72 + tok]       = __low2half(vv);
            svt[h][(d2 + 1) * 72 + tok] = __high2half(vv);
        }
        __syncthreads();

        const int head = p * 2 + hw;
        const float* rp = &srpb[head * 169];
        const uint32_t qb = smem_u32(sq[hw]);
        const uint32_t kb = smem_u32(skk[hw]);
        const uint32_t vb = smem_u32(svt[hw]);

        float Cs[8][4];
#pragma unroll
        for (int f = 0; f < 8; f++)
#pragma unroll
            for (int s = 0; s < 4; s++) Cs[f][s] = 0.f;
#pragma unroll
        for (int k16 = 0; k16 < 2; k16++) {
            uint32_t Ah[4];
            ldm4(Ah, qb + ((mb * 16 + (lane & 15)) * 40 + (lane >> 4) * 8 + k16 * 16) * 2);
#pragma unroll
            for (int g = 0; g < 4; g++) {
                uint32_t Bf[4];
                ldm4(Bf, kb + ((g * 16 + (lane & 7) + ((lane >> 4) & 1) * 8) * 40
                               + ((lane >> 3) & 1) * 8 + k16 * 16) * 2);
                mma16816(Cs[g * 2 + 0], Ah, Bf[0], Bf[1]);
                mma16816(Cs[g * 2 + 1], Ah, Bf[2], Bf[3]);
            }
        }

        const int li0 = slabel[i0];
        const int li1 = slabel[i1];
#pragma unroll
        for (int f = 0; f < 8; f++) {
            int jb = f * 8 + (lane & 3) * 2;
#pragma unroll
            for (int s = 0; s < 2; s++) {
                int j = jb + s;
                if (j < NTOK) {
                    int rj = j / WS_, cj = j - rj * WS_;
                    int lj = slabel[j];
                    if (i0 < NTOK) {
                        float b0 = rp[(ri0 - rj + 6) * 13 + (ci0 - cj + 6)];
                        Cs[f][s] += b0 - (li0 != lj ? 100.f : 0.f);
                    } else Cs[f][s] = -1e30f;
                    if (i1 < NTOK) {
                        float b1 = rp[(ri1 - rj + 6) * 13 + (ci1 - cj + 6)];
                        Cs[f][2 + s] += b1 - (li1 != lj ? 100.f : 0.f);
                    } else Cs[f][2 + s] = -1e30f;
                } else {
                    Cs[f][s] = -1e30f;
                    Cs[f][2 + s] = -1e30f;
                }
            }
        }

        float mx0 = -1e30f, mx1 = -1e30f;
#pragma unroll
        for (int f = 0; f < 8; f++) {
            mx0 = fmaxf(mx0, fmaxf(Cs[f][0], Cs[f][1]));
            mx1 = fmaxf(mx1, fmaxf(Cs[f][2], Cs[f][3]));
        }
        mx0 = fmaxf(mx0, __shfl_xor_sync(0xffffffffu, mx0, 1));
        mx0 = fmaxf(mx0, __shfl_xor_sync(0xffffffffu, mx0, 2));
        mx1 = fmaxf(mx1, __shfl_xor_sync(0xffffffffu, mx1, 1));
        mx1 = fmaxf(mx1, __shfl_xor_sync(0xffffffffu, mx1, 2));
        float sum0 = 0.f, sum1 = 0.f;
#pragma unroll
        for (int f = 0; f < 8; f++) {
            Cs[f][0] = __expf(Cs[f][0] - mx0);
            Cs[f][1] = __expf(Cs[f][1] - mx0);
            Cs[f][2] = __expf(Cs[f][2] - mx1);
            Cs[f][3] = __expf(Cs[f][3] - mx1);
            sum0 += Cs[f][0] + Cs[f][1];
            sum1 += Cs[f][2] + Cs[f][3];
        }
        sum0 += __shfl_xor_sync(0xffffffffu, sum0, 1);
        sum0 += __shfl_xor_sync(0xffffffffu, sum0, 2);
        sum1 += __shfl_xor_sync(0xffffffffu, sum1, 1);
        sum1 += __shfl_xor_sync(0xffffffffu, sum1, 2);
        const float inv0 = 1.f / sum0;
        const float inv1 = 1.f / sum1;

        uint32_t Pa[4][4];
#pragma unroll
        for (int f2 = 0; f2 < 4; f2++) {
            Pa[f2][0] = h2u(__floats2half2_rn(Cs[2 * f2][0],     Cs[2 * f2][1]));
            Pa[f2][1] = h2u(__floats2half2_rn(Cs[2 * f2][2],     Cs[2 * f2][3]));
            Pa[f2][2] = h2u(__floats2half2_rn(Cs[2 * f2 + 1][0], Cs[2 * f2 + 1][1]));
            Pa[f2][3] = h2u(__floats2half2_rn(Cs[2 * f2 + 1][2], Cs[2 * f2 + 1][3]));
        }

        float Co[4][4];
#pragma unroll
        for (int f = 0; f < 4; f++)
#pragma unroll
            for (int s = 0; s < 4; s++) Co[f][s] = 0.f;
#pragma unroll
        for (int k16 = 0; k16 < 4; k16++) {
#pragma unroll
            for (int g = 0; g < 2; g++) {
                uint32_t Bv[4];
                ldm4(Bv, vb + ((g * 16 + (lane & 7) + ((lane >> 4) & 1) * 8) * 72
                               + ((lane >> 3) & 1) * 8 + k16 * 16) * 2);
                mma16816(Co[g * 2 + 0], Pa[k16], Bv[0], Bv[1]);
                mma16816(Co[g * 2 + 1], Pa[k16], Bv[2], Bv[3]);
            }
        }

#pragma unroll
        for (int f = 0; f < 4; f++) {
            int d = f * 8 + (lane & 3) * 2;
            if (i0 < NTOK)
                *(__half2*)(g_attn + (size_t)(bwin * NTOK + i0) * CC + head * 32 + d) =
                    __floats2half2_rn(Co[f][0] * inv0, Co[f][1] * inv0);
            if (i1 < NTOK)
                *(__half2*)(g_attn + (size_t)(bwin * NTOK + i1) * CC + head * 32 + d) =
                    __floats2half2_rn(Co[f][2] * inv1, Co[f][3] * inv1);
        }
    }
}

// ------------------------------- launch -------------------------------------
extern "C" void kernel_launch(void* const* d_in, const int* in_sizes, int n_in,
                              void* d_out, int out_size) {
    const float* x       = (const float*)d_in[0];
    const float* norm1_w = (const float*)d_in[1];
    const float* norm1_b = (const float*)d_in[2];
    const float* qkv_w   = (const float*)d_in[3];
    const float* qkv_b   = (const float*)d_in[4];
    const float* rpb     = (const float*)d_in[5];
    const float* proj_w  = (const float*)d_in[6];
    const float* proj_b  = (const float*)d_in[7];
    const float* norm2_w = (const float*)d_in[8];
    const float* norm2_b = (const float*)d_in[9];
    const float* fc1_w   = (const float*)d_in[10];
    const float* fc1_b   = (const float*)d_in[11];
    const float* fc2_w   = (const float*)d_in[12];
    const float* fc2_b   = (const float*)d_in[13];
    float* out = (float*)d_out;

    __half *p_ln, *p_attn, *p_hid, *p_wqkv, *p_wproj, *p_wfc1, *p_wfc2;
    float *p_xnew;
    cudaGetSymbolAddress((void**)&p_ln,    g_ln);
    cudaGetSymbolAddress((void**)&p_attn,  g_attn);
    cudaGetSymbolAddress((void**)&p_hid,   g_hid);
    cudaGetSymbolAddress((void**)&p_xnew,  g_xnew);
    cudaGetSymbolAddress((void**)&p_wqkv,  g_wqkv);
    cudaGetSymbolAddress((void**)&p_wproj, g_wproj);
    cudaGetSymbolAddress((void**)&p_wfc1,  g_wfc1);
    cudaGetSymbolAddress((void**)&p_wfc2,  g_wfc2);

    const int BSM = 98304;   // 96 KB
    cudaFuncSetAttribute(bres_gemm<0,576>, cudaFuncAttributeMaxDynamicSharedMemorySize, BSM);
    cudaFuncSetAttribute(bres_gemm<1,192>, cudaFuncAttributeMaxDynamicSharedMemorySize, BSM);
    cudaFuncSetAttribute(bres_gemm<2,768>, cudaFuncAttributeMaxDynamicSharedMemorySize, BSM);
    cudaFuncSetAttribute(mma_gemm_fc2<768,192>, cudaFuncAttributeMaxDynamicSharedMemorySize, 3 * STAGE_B);

    // QKV bres GEMM at launch index 3 for ncu capture
    ln_kernel<<<MROWS / 8, 256>>>(x, norm1_w, norm1_b, p_ln);                     // 0
    whalf_kernel<<<(640 * 192 + 255) / 256, 256>>>(qkv_w, p_wqkv, 192, 576, 640); // 1
    whalf_kernel<<<(256 * 192 + 255) / 256, 256>>>(proj_w, p_wproj, 192, 192, 256); // 2
    bres_gemm<0,576><<<dim3(5, 196), 256, BSM>>>(p_ln, p_wqkv, qkv_b, nullptr);   // 3

    attn_kernel<<<NWIN, 256>>>(rpb);                                              // 4

    bres_gemm<1,192><<<dim3(2, 196), 256, BSM>>>(p_attn, p_wproj, proj_b, x);     // 5

    ln_kernel<<<MROWS / 8, 256>>>(p_xnew, norm2_w, norm2_b, p_ln);                // 6

    whalf_kernel<<<(768 * 192 + 255) / 256, 256>>>(fc1_w, p_wfc1, 192, 768, 768); // 7
    bres_gemm<2,768><<<dim3(6, 196), 256, BSM>>>(p_ln, p_wfc1, fc1_b, nullptr);   // 8

    whalf_kernel<<<(256 * 768 + 255) / 256, 256>>>(fc2_w, p_wfc2, 768, 192, 256); // 9
    mma_gemm_fc2<768,192><<<dim3(2, 1568), 256, 3 * STAGE_B>>>(p_hid, p_wfc2, fc2_b, out); // 10
}

// round 11
// speedup vs baseline: 1.0721x; 1.0721x over previous
#include <cuda_runtime.h>
#include <cuda_fp16.h>
#include <math.h>
#include <stdint.h>

// ---------------------------------------------------------------------------
// Swin block: fp16 HMMA GEMMs — B-resident (T=4) for QKV/fc1, streaming for
// proj/fc2; tensorized attention, one block per (window, head-pair).
// ---------------------------------------------------------------------------

#define BATCH   64
#define HH      56
#define WW_     56
#define CC      192
#define WS_     7
#define SS_     3
#define NH_     6
#define HD_     32
#define NTOK    49
#define NWIN    4096
#define MROWS   200704
#define HIDDEN  768
#define EPS_    1e-5f

// ------------------------------- scratch -----------------------------------
__device__ __half g_ln  [(size_t)MROWS * 192];
__device__ __half g_attn[(size_t)MROWS * 192];
__device__ __half g_hid [(size_t)MROWS * 768];
__device__ __half g_qkv [(size_t)MROWS * 576];
__device__ float g_xnew[(size_t)MROWS * CC];
__device__ __half g_wqkv [640 * 192];
__device__ __half g_wproj[256 * 192];
__device__ __half g_wfc1 [768 * 192];
__device__ __half g_wfc2 [256 * 768];

// ------------------------------ helpers -------------------------------------
__device__ __forceinline__ uint32_t smem_u32(const void* p) {
    uint32_t a;
    asm("{ .reg .u64 t; cvta.to.shared.u64 t, %1; cvt.u32.u64 %0, t; }"
        : "=r"(a) : "l"(p));
    return a;
}
#define SWZ(o) ((o) ^ (((o) >> 3) & 0x70))

__device__ __forceinline__ void cp16(uint32_t dst, const void* src) {
    asm volatile("cp.async.cg.shared.global [%0], [%1], 16;"
                 :: "r"(dst), "l"(src));
}
__device__ __forceinline__ void cp_commit() {
    asm volatile("cp.async.commit_group;" ::: "memory");
}
__device__ __forceinline__ void cp_wait1() {
    asm volatile("cp.async.wait_group 1;" ::: "memory");
}
__device__ __forceinline__ void ldm4(uint32_t* r, uint32_t addr) {
    asm volatile("ldmatrix.sync.aligned.m8n8.x4.shared.b16 {%0,%1,%2,%3}, [%4];"
                 : "=r"(r[0]), "=r"(r[1]), "=r"(r[2]), "=r"(r[3]) : "r"(addr));
}
__device__ __forceinline__ void mma16816(float* c, const uint32_t* a,
                                         uint32_t b0, uint32_t b1) {
    asm volatile(
        "mma.sync.aligned.m16n8k16.row.col.f32.f16.f16.f32 "
        "{%0,%1,%2,%3}, {%4,%5,%6,%7}, {%8,%9}, {%0,%1,%2,%3};"
        : "+f"(c[0]), "+f"(c[1]), "+f"(c[2]), "+f"(c[3])
        : "r"(a[0]), "r"(a[1]), "r"(a[2]), "r"(a[3]), "r"(b0), "r"(b1));
}
__device__ __forceinline__ uint32_t h2u(__half2 v) { return *(uint32_t*)&v; }

__device__ __forceinline__ int rowmap_of(int m) {
    int bwin = m / NTOK, tok = m - bwin * NTOK;
    int b = bwin >> 6, w = bwin & 63;
    int wh = w >> 3, ww = w & 7;
    int r = tok / WS_, c = tok - r * WS_;
    int oh = wh * WS_ + r + SS_; if (oh >= HH)  oh -= HH;
    int ow = ww * WS_ + c + SS_; if (ow >= WW_) ow -= WW_;
    return b * (HH * WW_) + oh * WW_ + ow;
}

// -------------------------- small prep kernels ------------------------------
__global__ void whalf_kernel(const float* __restrict__ W,
                             __half* __restrict__ out, int Kd, int Nd, int NP) {
    int idx = blockIdx.x * 256 + threadIdx.x;
    if (idx >= NP * Kd) return;
    int n = idx / Kd, k = idx - n * Kd;
    out[idx] = (n < Nd) ? __float2half(W[(size_t)k * Nd + n]) : __half(0);
}

__global__ void ln_kernel(const float* __restrict__ in,
                          const float* __restrict__ w,
                          const float* __restrict__ b,
                          __half* __restrict__ out) {
    int row  = blockIdx.x * 8 + (threadIdx.x >> 5);
    int lane = threadIdx.x & 31;
    const float* p = in + (size_t)row * CC;
    float v[6];
    float s = 0.f;
#pragma unroll
    for (int i = 0; i < 6; i++) { v[i] = p[lane + 32 * i]; s += v[i]; }
#pragma unroll
    for (int o = 16; o > 0; o >>= 1) s += __shfl_xor_sync(0xffffffffu, s, o);
    float mean = s * (1.f / CC);
    float q = 0.f;
#pragma unroll
    for (int i = 0; i < 6; i++) { float d = v[i] - mean; q += d * d; }
#pragma unroll
    for (int o = 16; o > 0; o >>= 1) q += __shfl_xor_sync(0xffffffffu, q, o);
    float inv = rsqrtf(q * (1.f / CC) + EPS_);
    __half* op = out + (size_t)row * CC;
#pragma unroll
    for (int i = 0; i < 6; i++) {
        int c = lane + 32 * i;
        op[c] = __float2half((v[i] - mean) * inv * w[c] + b[c]);
    }
}

// ------------------- B-resident GEMM (K=192, T M-tiles/CTA) ------------------
// MODE 0: QKV gather->g_qkv;  MODE 2: fc1+GELU->g_hid.
#define TTILES 4
template<int MODE, int NREAL>
__global__ __launch_bounds__(256, 2)
void bres_gemm(const __half* __restrict__ A,
               const __half* __restrict__ Bhi,
               const float* __restrict__ bias)
{
    extern __shared__ __align__(128) char dynsm[];
    constexpr int K = 192;
    constexpr int NITER = 3 * TTILES;

    const int tid  = threadIdx.x;
    const int lane = tid & 31;
    const int warp = tid >> 5;
    const int wm = warp & 3;
    const int wn = warp >> 2;
    const int blockN  = blockIdx.x * 128;
    const int blockM0 = blockIdx.y * (TTILES * 128);
    const uint32_t sbB = smem_u32(dynsm);
    const uint32_t sbA = sbB + 49152;

#pragma unroll
    for (int i = 0; i < 12; i++) {
        int idx = i * 256 + tid;
        int chunk = idx >> 10, rem = idx & 1023;
        int n = rem >> 3, u = rem & 7;
        cp16(sbB + chunk * 16384 + SWZ((uint32_t)(n * 128 + u * 16)),
             Bhi + (size_t)(blockN + n) * K + chunk * 64 + u * 8);
    }

    int aRow[4];
    uint32_t aDst[4];
#pragma unroll
    for (int i = 0; i < 4; i++) {
        int idx = i * 256 + tid;
        aRow[i] = idx >> 3;
        int u = idx & 7;
        aDst[i] = SWZ((uint32_t)(aRow[i] * 128 + u * 16));
    }
    const int aCol = (tid & 7) * 8;

    auto issueA = [&](int tc) {
        int t = tc / 3, c = tc - t * 3;
        const uint32_t sb = sbA + (tc % 3) * 16384;
        int mbase = blockM0 + t * 128;
#pragma unroll
        for (int i = 0; i < 4; i++) {
            int m = mbase + aRow[i];
            int gm = (MODE == 0) ? rowmap_of(m) : m;
            cp16(sb + aDst[i], A + (size_t)gm * K + c * 64 + aCol);
        }
    };

    uint32_t oA[2], oB[4];
#pragma unroll
    for (int tm = 0; tm < 2; tm++)
        oA[tm] = (uint32_t)((wm * 32 + tm * 16 + (lane & 15)) * 128 + (lane >> 4) * 16);
#pragma unroll
    for (int g = 0; g < 4; g++)
        oB[g] = (uint32_t)((wn * 64 + g * 16 + (lane & 7) + ((lane >> 4) & 1) * 8) * 128
                           + ((lane >> 3) & 1) * 16);

    float Cr[2][8][4];
#pragma unroll
    for (int a = 0; a < 2; a++)
#pragma unroll
        for (int b = 0; b < 8; b++)
#pragma unroll
            for (int c = 0; c < 4; c++) Cr[a][b][c] = 0.f;

    issueA(0); cp_commit();
    issueA(1); cp_commit();

    const int r0l = wm * 32 + (lane >> 2);
    const int n0 = blockN + wn * 64 + 2 * (lane & 3);

    for (int tc = 0; tc < NITER; tc++) {
        const int c = tc % 3;
        cp_wait1();
        __syncthreads();
        if (tc + 2 < NITER) { issueA(tc + 2); cp_commit(); }

        const uint32_t aB = sbA + (tc % 3) * 16384;
        const uint32_t bB = sbB + c * 16384;
#pragma unroll
        for (int k16 = 0; k16 < 4; k16++) {
            const uint32_t ko = k16 * 32;
            uint32_t Ah[2][4], Bh[4][4];
#pragma unroll
            for (int tm = 0; tm < 2; tm++)
                ldm4(Ah[tm], aB + SWZ(oA[tm] + ko));
#pragma unroll
            for (int g = 0; g < 4; g++)
                ldm4(Bh[g], bB + SWZ(oB[g] + ko));
#pragma unroll
            for (int tm = 0; tm < 2; tm++)
#pragma unroll
                for (int tn = 0; tn < 8; tn++)
                    mma16816(Cr[tm][tn], Ah[tm],
                             Bh[tn >> 1][(tn & 1) * 2], Bh[tn >> 1][(tn & 1) * 2 + 1]);
        }

        if (c == 2) {
            const int mb = blockM0 + (tc / 3) * 128;
#pragma unroll
            for (int tm = 0; tm < 2; tm++) {
#pragma unroll
                for (int tn = 0; tn < 8; tn++) {
                    int n = n0 + tn * 8;
                    if (n >= NREAL) continue;
                    float bx = bias[n], by = bias[n + 1];
#pragma unroll
                    for (int half_ = 0; half_ < 2; half_++) {
                        int m = mb + r0l + tm * 16 + half_ * 8;
                        float vx = Cr[tm][tn][half_ * 2 + 0] + bx;
                        float vy = Cr[tm][tn][half_ * 2 + 1] + by;
                        if (MODE == 0) {
                            *(__half2*)(g_qkv + (size_t)m * 576 + n) =
                                __floats2half2_rn(vx, vy);
                        } else {
                            vx = 0.5f * vx * (1.f + erff(vx * 0.70710678118654752f));
                            vy = 0.5f * vy * (1.f + erff(vy * 0.70710678118654752f));
                            *(__half2*)(g_hid + (size_t)m * HIDDEN + n) =
                                __floats2half2_rn(vx, vy);
                        }
                    }
                }
            }
#pragma unroll
            for (int a = 0; a < 2; a++)
#pragma unroll
                for (int b = 0; b < 8; b++)
#pragma unroll
                    for (int cc2 = 0; cc2 < 4; cc2++) Cr[a][b][cc2] = 0.f;
        }
    }
}

// ----------------- streaming GEMM (proj MODE1, fc2 MODE3) --------------------
#define STAGE_B 32768
template<int K, int MODE, int NREAL>
__global__ __launch_bounds__(256, 2)
void mma_gemm(const __half* __restrict__ A,
              const __half* __restrict__ Bhi,
              const float* __restrict__ bias,
              const float* __restrict__ aux,
              float* __restrict__ outp)
{
    extern __shared__ __align__(128) char dynsm[];
    constexpr int NCH = K / 64;

    const int tid  = threadIdx.x;
    const int lane = tid & 31;
    const int warp = tid >> 5;
    const int wm = warp & 3;
    const int wn = warp >> 2;
    const int blockN = blockIdx.x * 128;
    const int blockM = blockIdx.y * 128;
    const uint32_t sb0 = smem_u32(dynsm);

    const __half* aSrc[4];
    uint32_t aDst[4];
#pragma unroll
    for (int i = 0; i < 4; i++) {
        int idx = i * 256 + tid;
        int row = idx >> 3, u = idx & 7;
        aSrc[i] = A + (size_t)(blockM + row) * K + u * 8;
        aDst[i] = SWZ((uint32_t)(row * 128 + u * 16));
    }
    const __half* bSrc[4];
    uint32_t bDst[4];
#pragma unroll
    for (int i = 0; i < 4; i++) {
        int idx = i * 256 + tid;
        int n = idx >> 3, u = idx & 7;
        bSrc[i] = Bhi + (size_t)(blockN + n) * K + u * 8;
        bDst[i] = SWZ((uint32_t)(n * 128 + u * 16));
    }

    auto issue = [&](int c, int st) {
        const uint32_t sb = sb0 + st * STAGE_B;
#pragma unroll
        for (int i = 0; i < 4; i++)
            cp16(sb + aDst[i], aSrc[i] + c * 64);
#pragma unroll
        for (int i = 0; i < 4; i++)
            cp16(sb + 16384 + bDst[i], bSrc[i] + c * 64);
    };

    uint32_t oA[2], oB[4];
#pragma unroll
    for (int tm = 0; tm < 2; tm++)
        oA[tm] = (uint32_t)((wm * 32 + tm * 16 + (lane & 15)) * 128 + (lane >> 4) * 16);
#pragma unroll
    for (int g = 0; g < 4; g++)
        oB[g] = (uint32_t)((wn * 64 + g * 16 + (lane & 7) + ((lane >> 4) & 1) * 8) * 128
                           + ((lane >> 3) & 1) * 16);

    float Cr[2][8][4];
#pragma unroll
    for (int a = 0; a < 2; a++)
#pragma unroll
        for (int b = 0; b < 8; b++)
#pragma unroll
            for (int c = 0; c < 4; c++) Cr[a][b][c] = 0.f;

    issue(0, 0); cp_commit();
    if (NCH > 1) issue(1, 1);
    cp_commit();

    for (int c = 0; c < NCH; c++) {
        const int st = c % 3;
        cp_wait1();
        __syncthreads();
        if (c + 2 < NCH) { issue(c + 2, (c + 2) % 3); cp_commit(); }

        const uint32_t aB = sb0 + st * STAGE_B;
        const uint32_t bB = aB + 16384;
#pragma unroll
        for (int k16 = 0; k16 < 4; k16++) {
            const uint32_t ko = k16 * 32;
            uint32_t Ah[2][4], Bh[4][4];
#pragma unroll
            for (int tm = 0; tm < 2; tm++)
                ldm4(Ah[tm], aB + SWZ(oA[tm] + ko));
#pragma unroll
            for (int g = 0; g < 4; g++)
                ldm4(Bh[g], bB + SWZ(oB[g] + ko));
#pragma unroll
            for (int tm = 0; tm < 2; tm++)
#pragma unroll
                for (int tn = 0; tn < 8; tn++)
                    mma16816(Cr[tm][tn], Ah[tm],
                             Bh[tn >> 1][(tn & 1) * 2], Bh[tn >> 1][(tn & 1) * 2 + 1]);
        }
    }

    const int r0 = blockM + wm * 32 + (lane >> 2);
    const int n0 = blockN + wn * 64 + 2 * (lane & 3);
#pragma unroll
    for (int tm = 0; tm < 2; tm++) {
#pragma unroll
        for (int tn = 0; tn < 8; tn++) {
            int n = n0 + tn * 8;
            if (n >= NREAL) continue;
            float bx = bias[n], by = bias[n + 1];
#pragma unroll
            for (int half_ = 0; half_ < 2; half_++) {
                int m = r0 + tm * 16 + half_ * 8;
                float vx = Cr[tm][tn][half_ * 2 + 0] + bx;
                float vy = Cr[tm][tn][half_ * 2 + 1] + by;
                if (MODE == 1) {
                    size_t idx = (size_t)rowmap_of(m) * CC + n;
                    float2 a = *(const float2*)(aux + idx);
                    *(float2*)(g_xnew + idx) = make_float2(vx + a.x, vy + a.y);
                } else {
                    size_t idx = (size_t)m * CC + n;
                    float2 a = *(const float2*)(g_xnew + idx);
                    *(float2*)(outp + idx) = make_float2(vx + a.x, vy + a.y);
                }
            }
        }
    }
}

// ------------------------------ attention (HMMA) -----------------------------
// grid (NWIN, 3): one block per (window, head pair). 8 warps = 2 heads x 4 mb.
__global__ __launch_bounds__(256)
void attn_kernel(const float* __restrict__ rpb) {
    __shared__ __align__(16) __half sq [2][64 * 40];
    __shared__ __align__(16) __half skk[2][64 * 40];
    __shared__ __align__(16) __half svt[2][32 * 72];
    __shared__ float srpb[2 * 169];
    __shared__ int   slabel[64];

    const int bwin = blockIdx.x;
    const int p    = blockIdx.y;
    const int tid  = threadIdx.x;
    const int lane = tid & 31;
    const int warp = tid >> 5;
    const int hw = warp >> 2;
    const int mb = warp & 3;
    const float scale = 0.17677669529663687f;

    for (int idx = tid; idx < 2 * 169; idx += 256)
        srpb[idx] = rpb[(idx % 169) * NH_ + p * 2 + idx / 169];
    if (tid < 64) {
        int label = 0;
        if (tid < NTOK) {
            int w = bwin & 63;
            int wh = w >> 3, ww = w & 7;
            int r = tid / WS_, c = tid - r * WS_;
            int gh = wh * WS_ + r, gw = ww * WS_ + c;
            int rr = (gh < HH - WS_) ? 0 : (gh < HH - SS_) ? 1 : 2;
            int cc = (gw < WW_ - WS_) ? 0 : (gw < WW_ - SS_) ? 1 : 2;
            label = rr * 3 + cc;
        }
        slabel[tid] = label;
    }
    for (int t = tid; t < (2 * 32 * 72) / 2; t += 256)
        ((uint32_t*)svt)[t] = 0;
    __syncthreads();

    for (int idx = tid; idx < 2 * NTOK * 16; idx += 256) {
        int h = (idx >= NTOK * 16);
        int rem = idx - h * NTOK * 16;
        int tok = rem >> 4, d2 = (rem & 15) * 2;
        const __half* src = g_qkv + (size_t)(bwin * NTOK + tok) * 576
                            + (p * 2 + h) * 32 + d2;
        float2 qf = __half22float2(*(const __half2*)src);
        *(__half2*)(&sq[h][tok * 40 + d2]) = __floats2half2_rn(qf.x * scale, qf.y * scale);
        *(__half2*)(&skk[h][tok * 40 + d2]) = *(const __half2*)(src + 192);
        __half2 vv = *(const __half2*)(src + 384);
        svt[h][d2 * 72 + tok]       = __low2half(vv);
        svt[h][(d2 + 1) * 72 + tok] = __high2half(vv);
    }
    __syncthreads();

    const int head = p * 2 + hw;
    const float* rp = &srpb[hw * 169];
    const uint32_t qb = smem_u32(sq[hw]);
    const uint32_t kb = smem_u32(skk[hw]);
    const uint32_t vb = smem_u32(svt[hw]);

    const int i0 = mb * 16 + (lane >> 2);
    const int i1 = i0 + 8;
    const int ri0 = i0 / WS_, ci0 = i0 - ri0 * WS_;
    const int ri1 = i1 / WS_, ci1 = i1 - ri1 * WS_;

    float Cs[8][4];
#pragma unroll
    for (int f = 0; f < 8; f++)
#pragma unroll
        for (int s = 0; s < 4; s++) Cs[f][s] = 0.f;
#pragma unroll
    for (int k16 = 0; k16 < 2; k16++) {
        uint32_t Ah[4];
        ldm4(Ah, qb + ((mb * 16 + (lane & 15)) * 40 + (lane >> 4) * 8 + k16 * 16) * 2);
#pragma unroll
        for (int g = 0; g < 4; g++) {
            uint32_t Bf[4];
            ldm4(Bf, kb + ((g * 16 + (lane & 7) + ((lane >> 4) & 1) * 8) * 40
                           + ((lane >> 3) & 1) * 8 + k16 * 16) * 2);
            mma16816(Cs[g * 2 + 0], Ah, Bf[0], Bf[1]);
            mma16816(Cs[g * 2 + 1], Ah, Bf[2], Bf[3]);
        }
    }

    const int li0 = slabel[i0];
    const int li1 = slabel[i1];
#pragma unroll
    for (int f = 0; f < 8; f++) {
        int jb = f * 8 + (lane & 3) * 2;
#pragma unroll
        for (int s = 0; s < 2; s++) {
            int j = jb + s;
            if (j < NTOK) {
                int rj = j / WS_, cj = j - rj * WS_;
                int lj = slabel[j];
                if (i0 < NTOK) {
                    float b0 = rp[(ri0 - rj + 6) * 13 + (ci0 - cj + 6)];
                    Cs[f][s] += b0 - (li0 != lj ? 100.f : 0.f);
                } else Cs[f][s] = -1e30f;
                if (i1 < NTOK) {
                    float b1 = rp[(ri1 - rj + 6) * 13 + (ci1 - cj + 6)];
                    Cs[f][2 + s] += b1 - (li1 != lj ? 100.f : 0.f);
                } else Cs[f][2 + s] = -1e30f;
            } else {
                Cs[f][s] = -1e30f;
                Cs[f][2 + s] = -1e30f;
            }
        }
    }

    float mx0 = -1e30f, mx1 = -1e30f;
#pragma unroll
    for (int f = 0; f < 8; f++) {
        mx0 = fmaxf(mx0, fmaxf(Cs[f][0], Cs[f][1]));
        mx1 = fmaxf(mx1, fmaxf(Cs[f][2], Cs[f][3]));
    }
    mx0 = fmaxf(mx0, __shfl_xor_sync(0xffffffffu, mx0, 1));
    mx0 = fmaxf(mx0, __shfl_xor_sync(0xffffffffu, mx0, 2));
    mx1 = fmaxf(mx1, __shfl_xor_sync(0xffffffffu, mx1, 1));
    mx1 = fmaxf(mx1, __shfl_xor_sync(0xffffffffu, mx1, 2));
    float sum0 = 0.f, sum1 = 0.f;
#pragma unroll
    for (int f = 0; f < 8; f++) {
        Cs[f][0] = __expf(Cs[f][0] - mx0);
        Cs[f][1] = __expf(Cs[f][1] - mx0);
        Cs[f][2] = __expf(Cs[f][2] - mx1);
        Cs[f][3] = __expf(Cs[f][3] - mx1);
        sum0 += Cs[f][0] + Cs[f][1];
        sum1 += Cs[f][2] + Cs[f][3];
    }
    sum0 += __shfl_xor_sync(0xffffffffu, sum0, 1);
    sum0 += __shfl_xor_sync(0xffffffffu, sum0, 2);
    sum1 += __shfl_xor_sync(0xffffffffu, sum1, 1);
    sum1 += __shfl_xor_sync(0xffffffffu, sum1, 2);
    const float inv0 = 1.f / sum0;
    const float inv1 = 1.f / sum1;

    uint32_t Pa[4][4];
#pragma unroll
    for (int f2 = 0; f2 < 4; f2++) {
        Pa[f2][0] = h2u(__floats2half2_rn(Cs[2 * f2][0],     Cs[2 * f2][1]));
        Pa[f2][1] = h2u(__floats2half2_rn(Cs[2 * f2][2],     Cs[2 * f2][3]));
        Pa[f2][2] = h2u(__floats2half2_rn(Cs[2 * f2 + 1][0], Cs[2 * f2 + 1][1]));
        Pa[f2][3] = h2u(__floats2half2_rn(Cs[2 * f2 + 1][2], Cs[2 * f2 + 1][3]));
    }

    float Co[4][4];
#pragma unroll
    for (int f = 0; f < 4; f++)
#pragma unroll
        for (int s = 0; s < 4; s++) Co[f][s] = 0.f;
#pragma unroll
    for (int k16 = 0; k16 < 4; k16++) {
#pragma unroll
        for (int g = 0; g < 2; g++) {
            uint32_t Bv[4];
            ldm4(Bv, vb + ((g * 16 + (lane & 7) + ((lane >> 4) & 1) * 8) * 72
                           + ((lane >> 3) & 1) * 8 + k16 * 16) * 2);
            mma16816(Co[g * 2 + 0], Pa[k16], Bv[0], Bv[1]);
            mma16816(Co[g * 2 + 1], Pa[k16], Bv[2], Bv[3]);
        }
    }

#pragma unroll
    for (int f = 0; f < 4; f++) {
        int d = f * 8 + (lane & 3) * 2;
        if (i0 < NTOK)
            *(__half2*)(g_attn + (size_t)(bwin * NTOK + i0) * CC + head * 32 + d) =
                __floats2half2_rn(Co[f][0] * inv0, Co[f][1] * inv0);
        if (i1 < NTOK)
            *(__half2*)(g_attn + (size_t)(bwin * NTOK + i1) * CC + head * 32 + d) =
                __floats2half2_rn(Co[f][2] * inv1, Co[f][3] * inv1);
    }
}

// ------------------------------- launch -------------------------------------
extern "C" void kernel_launch(void* const* d_in, const int* in_sizes, int n_in,
                              void* d_out, int out_size) {
    const float* x       = (const float*)d_in[0];
    const float* norm1_w = (const float*)d_in[1];
    const float* norm1_b = (const float*)d_in[2];
    const float* qkv_w   = (const float*)d_in[3];
    const float* qkv_b   = (const float*)d_in[4];
    const float* rpb     = (const float*)d_in[5];
    const float* proj_w  = (const float*)d_in[6];
    const float* proj_b  = (const float*)d_in[7];
    const float* norm2_w = (const float*)d_in[8];
    const float* norm2_b = (const float*)d_in[9];
    const float* fc1_w   = (const float*)d_in[10];
    const float* fc1_b   = (const float*)d_in[11];
    const float* fc2_w   = (const float*)d_in[12];
    const float* fc2_b   = (const float*)d_in[13];
    float* out = (float*)d_out;

    __half *p_ln, *p_attn, *p_hid, *p_wqkv, *p_wproj, *p_wfc1, *p_wfc2;
    float *p_xnew;
    cudaGetSymbolAddress((void**)&p_ln,    g_ln);
    cudaGetSymbolAddress((void**)&p_attn,  g_attn);
    cudaGetSymbolAddress((void**)&p_hid,   g_hid);
    cudaGetSymbolAddress((void**)&p_xnew,  g_xnew);
    cudaGetSymbolAddress((void**)&p_wqkv,  g_wqkv);
    cudaGetSymbolAddress((void**)&p_wproj, g_wproj);
    cudaGetSymbolAddress((void**)&p_wfc1,  g_wfc1);
    cudaGetSymbolAddress((void**)&p_wfc2,  g_wfc2);

    const int BSM = 98304;
    cudaFuncSetAttribute(bres_gemm<0,576>, cudaFuncAttributeMaxDynamicSharedMemorySize, BSM);
    cudaFuncSetAttribute(bres_gemm<2,768>, cudaFuncAttributeMaxDynamicSharedMemorySize, BSM);
    cudaFuncSetAttribute(mma_gemm<192,1,192>, cudaFuncAttributeMaxDynamicSharedMemorySize, 3 * STAGE_B);
    cudaFuncSetAttribute(mma_gemm<768,3,192>, cudaFuncAttributeMaxDynamicSharedMemorySize, 3 * STAGE_B);

    ln_kernel<<<MROWS / 8, 256>>>(x, norm1_w, norm1_b, p_ln);                     // 0
    whalf_kernel<<<(640 * 192 + 255) / 256, 256>>>(qkv_w, p_wqkv, 192, 576, 640); // 1
    whalf_kernel<<<(256 * 192 + 255) / 256, 256>>>(proj_w, p_wproj, 192, 192, 256); // 2
    bres_gemm<0,576><<<dim3(5, 392), 256, BSM>>>(p_ln, p_wqkv, qkv_b);            // 3

    attn_kernel<<<dim3(NWIN, 3), 256>>>(rpb);                                     // 4

    mma_gemm<192,1,192><<<dim3(2, 1568), 256, 3 * STAGE_B>>>(p_attn, p_wproj, proj_b, x, nullptr); // 5

    ln_kernel<<<MROWS / 8, 256>>>(p_xnew, norm2_w, norm2_b, p_ln);                // 6

    whalf_kernel<<<(768 * 192 + 255) / 256, 256>>>(fc1_w, p_wfc1, 192, 768, 768); // 7
    bres_gemm<2,768><<<dim3(6, 392), 256, BSM>>>(p_ln, p_wfc1, fc1_b);            // 8

    whalf_kernel<<<(256 * 768 + 255) / 256, 256>>>(fc2_w, p_wfc2, 768, 192, 256); // 9
    mma_gemm<768,3,192><<<dim3(2, 1568), 256, 3 * STAGE_B>>>(p_hid, p_wfc2, fc2_b, nullptr, out); // 10
}

// round 13
// speedup vs baseline: 1.0967x; 1.0229x over previous
#include <cuda_runtime.h>
#include <cuda_fp16.h>
#include <math.h>
#include <stdint.h>

// ---------------------------------------------------------------------------
// Swin block: fp16 HMMA GEMMs — B-resident (T=4) QKV/fc1, streaming proj/fc2;
// tensorized attention (block per window x head-pair), q pre-scaled in QKV.
// ---------------------------------------------------------------------------

#define BATCH   64
#define HH      56
#define WW_     56
#define CC      192
#define WS_     7
#define SS_     3
#define NH_     6
#define HD_     32
#define NTOK    49
#define NWIN    4096
#define MROWS   200704
#define HIDDEN  768
#define EPS_    1e-5f

// ------------------------------- scratch -----------------------------------
__device__ __half g_ln  [(size_t)MROWS * 192];
__device__ __half g_attn[(size_t)MROWS * 192];
__device__ __half g_hid [(size_t)MROWS * 768];
__device__ __half g_qkv [(size_t)MROWS * 576];
__device__ float g_xnew[(size_t)MROWS * CC];
__device__ __half g_wqkv [640 * 192];
__device__ __half g_wproj[256 * 192];
__device__ __half g_wfc1 [768 * 192];
__device__ __half g_wfc2 [256 * 768];

// ------------------------------ helpers -------------------------------------
__device__ __forceinline__ uint32_t smem_u32(const void* p) {
    uint32_t a;
    asm("{ .reg .u64 t; cvta.to.shared.u64 t, %1; cvt.u32.u64 %0, t; }"
        : "=r"(a) : "l"(p));
    return a;
}
#define SWZ(o) ((o) ^ (((o) >> 3) & 0x70))

__device__ __forceinline__ void cp16(uint32_t dst, const void* src) {
    asm volatile("cp.async.cg.shared.global [%0], [%1], 16;"
                 :: "r"(dst), "l"(src));
}
__device__ __forceinline__ void cp_commit() {
    asm volatile("cp.async.commit_group;" ::: "memory");
}
__device__ __forceinline__ void cp_wait1() {
    asm volatile("cp.async.wait_group 1;" ::: "memory");
}
__device__ __forceinline__ void ldm4(uint32_t* r, uint32_t addr) {
    asm volatile("ldmatrix.sync.aligned.m8n8.x4.shared.b16 {%0,%1,%2,%3}, [%4];"
                 : "=r"(r[0]), "=r"(r[1]), "=r"(r[2]), "=r"(r[3]) : "r"(addr));
}
__device__ __forceinline__ void mma16816(float* c, const uint32_t* a,
                                         uint32_t b0, uint32_t b1) {
    asm volatile(
        "mma.sync.aligned.m16n8k16.row.col.f32.f16.f16.f32 "
        "{%0,%1,%2,%3}, {%4,%5,%6,%7}, {%8,%9}, {%0,%1,%2,%3};"
        : "+f"(c[0]), "+f"(c[1]), "+f"(c[2]), "+f"(c[3])
        : "r"(a[0]), "r"(a[1]), "r"(a[2]), "r"(a[3]), "r"(b0), "r"(b1));
}
__device__ __forceinline__ uint32_t h2u(__half2 v) { return *(uint32_t*)&v; }

__device__ __forceinline__ int rowmap_of(int m) {
    int bwin = m / NTOK, tok = m - bwin * NTOK;
    int b = bwin >> 6, w = bwin & 63;
    int wh = w >> 3, ww = w & 7;
    int r = tok / WS_, c = tok - r * WS_;
    int oh = wh * WS_ + r + SS_; if (oh >= HH)  oh -= HH;
    int ow = ww * WS_ + c + SS_; if (ow >= WW_) ow -= WW_;
    return b * (HH * WW_) + oh * WW_ + ow;
}

// -------------------------- prep kernels ------------------------------------
// merged weight conversion: 4 segments, fp32 [K,N] -> fp16 [NP,K] (zero pad)
__global__ void whalf_all(const float* __restrict__ w0, __half* __restrict__ o0,
                          const float* __restrict__ w1, __half* __restrict__ o1,
                          const float* __restrict__ w2, __half* __restrict__ o2,
                          const float* __restrict__ w3, __half* __restrict__ o3) {
    int gidx = blockIdx.x * 256 + threadIdx.x;
    const float* W; __half* out; int Kd, Nd, NP, idx;
    if (gidx < 122880)      { W = w0; out = o0; Kd = 192; Nd = 576; NP = 640; idx = gidx; }
    else if (gidx < 172032) { W = w1; out = o1; Kd = 192; Nd = 192; NP = 256; idx = gidx - 122880; }
    else if (gidx < 319488) { W = w2; out = o2; Kd = 192; Nd = 768; NP = 768; idx = gidx - 172032; }
    else if (gidx < 516096) { W = w3; out = o3; Kd = 768; Nd = 192; NP = 256; idx = gidx - 319488; }
    else return;
    int n = idx / Kd, k = idx - n * Kd;
    out[idx] = (n < Nd) ? __float2half(W[(size_t)k * Nd + n]) : __half(0);
}

__global__ void ln_kernel(const float* __restrict__ in,
                          const float* __restrict__ w,
                          const float* __restrict__ b,
                          __half* __restrict__ out) {
    int row  = blockIdx.x * 8 + (threadIdx.x >> 5);
    int lane = threadIdx.x & 31;
    const float* p = in + (size_t)row * CC;
    float v[6];
    float s = 0.f;
#pragma unroll
    for (int i = 0; i < 6; i++) { v[i] = p[lane + 32 * i]; s += v[i]; }
#pragma unroll
    for (int o = 16; o > 0; o >>= 1) s += __shfl_xor_sync(0xffffffffu, s, o);
    float mean = s * (1.f / CC);
    float q = 0.f;
#pragma unroll
    for (int i = 0; i < 6; i++) { float d = v[i] - mean; q += d * d; }
#pragma unroll
    for (int o = 16; o > 0; o >>= 1) q += __shfl_xor_sync(0xffffffffu, q, o);
    float inv = rsqrtf(q * (1.f / CC) + EPS_);
    __half* op = out + (size_t)row * CC;
#pragma unroll
    for (int i = 0; i < 6; i++) {
        int c = lane + 32 * i;
        op[c] = __float2half((v[i] - mean) * inv * w[c] + b[c]);
    }
}

// ------------------- B-resident GEMM (K=192, T M-tiles/CTA) ------------------
// MODE 0: QKV gather->g_qkv (q pre-scaled);  MODE 2: fc1+GELU->g_hid.
#define TTILES 4
template<int MODE, int NREAL>
__global__ __launch_bounds__(256, 2)
void bres_gemm(const __half* __restrict__ A,
               const __half* __restrict__ Bhi,
               const float* __restrict__ bias)
{
    extern __shared__ __align__(128) char dynsm[];
    constexpr int K = 192;
    constexpr int NITER = 3 * TTILES;

    const int tid  = threadIdx.x;
    const int lane = tid & 31;
    const int warp = tid >> 5;
    const int wm = warp & 3;
    const int wn = warp >> 2;
    const int blockN  = blockIdx.x * 128;
    const int blockM0 = blockIdx.y * (TTILES * 128);
    const uint32_t sbB = smem_u32(dynsm);
    const uint32_t sbA = sbB + 49152;

#pragma unroll
    for (int i = 0; i < 12; i++) {
        int idx = i * 256 + tid;
        int chunk = idx >> 10, rem = idx & 1023;
        int n = rem >> 3, u = rem & 7;
        cp16(sbB + chunk * 16384 + SWZ((uint32_t)(n * 128 + u * 16)),
             Bhi + (size_t)(blockN + n) * K + chunk * 64 + u * 8);
    }

    int aRow[4];
    uint32_t aDst[4];
#pragma unroll
    for (int i = 0; i < 4; i++) {
        int idx = i * 256 + tid;
        aRow[i] = idx >> 3;
        int u = idx & 7;
        aDst[i] = SWZ((uint32_t)(aRow[i] * 128 + u * 16));
    }
    const int aCol = (tid & 7) * 8;

    auto issueA = [&](int tc) {
        int t = tc / 3, c = tc - t * 3;
        const uint32_t sb = sbA + (tc % 3) * 16384;
        int mbase = blockM0 + t * 128;
#pragma unroll
        for (int i = 0; i < 4; i++) {
            int m = mbase + aRow[i];
            int gm = (MODE == 0) ? rowmap_of(m) : m;
            cp16(sb + aDst[i], A + (size_t)gm * K + c * 64 + aCol);
        }
    };

    uint32_t oA[2], oB[4];
#pragma unroll
    for (int tm = 0; tm < 2; tm++)
        oA[tm] = (uint32_t)((wm * 32 + tm * 16 + (lane & 15)) * 128 + (lane >> 4) * 16);
#pragma unroll
    for (int g = 0; g < 4; g++)
        oB[g] = (uint32_t)((wn * 64 + g * 16 + (lane & 7) + ((lane >> 4) & 1) * 8) * 128
                           + ((lane >> 3) & 1) * 16);

    float Cr[2][8][4];
#pragma unroll
    for (int a = 0; a < 2; a++)
#pragma unroll
        for (int b = 0; b < 8; b++)
#pragma unroll
            for (int c = 0; c < 4; c++) Cr[a][b][c] = 0.f;

    issueA(0); cp_commit();
    issueA(1); cp_commit();

    const int r0l = wm * 32 + (lane >> 2);
    const int n0 = blockN + wn * 64 + 2 * (lane & 3);

    for (int tc = 0; tc < NITER; tc++) {
        const int c = tc % 3;
        cp_wait1();
        __syncthreads();
        if (tc + 2 < NITER) { issueA(tc + 2); cp_commit(); }

        const uint32_t aB = sbA + (tc % 3) * 16384;
        const uint32_t bB = sbB + c * 16384;
#pragma unroll
        for (int k16 = 0; k16 < 4; k16++) {
            const uint32_t ko = k16 * 32;
            uint32_t Ah[2][4], Bh[4][4];
#pragma unroll
            for (int tm = 0; tm < 2; tm++)
                ldm4(Ah[tm], aB + SWZ(oA[tm] + ko));
#pragma unroll
            for (int g = 0; g < 4; g++)
                ldm4(Bh[g], bB + SWZ(oB[g] + ko));
#pragma unroll
            for (int tm = 0; tm < 2; tm++)
#pragma unroll
                for (int tn = 0; tn < 8; tn++)
                    mma16816(Cr[tm][tn], Ah[tm],
                             Bh[tn >> 1][(tn & 1) * 2], Bh[tn >> 1][(tn & 1) * 2 + 1]);
        }

        if (c == 2) {
            const int mb = blockM0 + (tc / 3) * 128;
#pragma unroll
            for (int tm = 0; tm < 2; tm++) {
#pragma unroll
                for (int tn = 0; tn < 8; tn++) {
                    int n = n0 + tn * 8;
                    if (n >= NREAL) continue;
                    float bx = bias[n], by = bias[n + 1];
#pragma unroll
                    for (int half_ = 0; half_ < 2; half_++) {
                        int m = mb + r0l + tm * 16 + half_ * 8;
                        float vx = Cr[tm][tn][half_ * 2 + 0] + bx;
                        float vy = Cr[tm][tn][half_ * 2 + 1] + by;
                        if (MODE == 0) {
                            if (n < 192) {      // pre-scale q by 1/sqrt(32)
                                vx *= 0.17677669529663687f;
                                vy *= 0.17677669529663687f;
                            }
                            *(__half2*)(g_qkv + (size_t)m * 576 + n) =
                                __floats2half2_rn(vx, vy);
                        } else {
                            vx = 0.5f * vx * (1.f + erff(vx * 0.70710678118654752f));
                            vy = 0.5f * vy * (1.f + erff(vy * 0.70710678118654752f));
                            *(__half2*)(g_hid + (size_t)m * HIDDEN + n) =
                                __floats2half2_rn(vx, vy);
                        }
                    }
                }
            }
#pragma unroll
            for (int a = 0; a < 2; a++)
#pragma unroll
                for (int b = 0; b < 8; b++)
#pragma unroll
                    for (int cc2 = 0; cc2 < 4; cc2++) Cr[a][b][cc2] = 0.f;
        }
    }
}

// ----------------- streaming GEMM (proj MODE1, fc2 MODE3) --------------------
#define STAGE_B 32768
template<int K, int MODE, int NREAL>
__global__ __launch_bounds__(256, 2)
void mma_gemm(const __half* __restrict__ A,
              const __half* __restrict__ Bhi,
              const float* __restrict__ bias,
              const float* __restrict__ aux,
              float* __restrict__ outp)
{
    extern __shared__ __align__(128) char dynsm[];
    constexpr int NCH = K / 64;

    const int tid  = threadIdx.x;
    const int lane = tid & 31;
    const int warp = tid >> 5;
    const int wm = warp & 3;
    const int wn = warp >> 2;
    const int blockN = blockIdx.x * 128;
    const int blockM = blockIdx.y * 128;
    const uint32_t sb0 = smem_u32(dynsm);

    const __half* aSrc[4];
    uint32_t aDst[4];
#pragma unroll
    for (int i = 0; i < 4; i++) {
        int idx = i * 256 + tid;
        int row = idx >> 3, u = idx & 7;
        aSrc[i] = A + (size_t)(blockM + row) * K + u * 8;
        aDst[i] = SWZ((uint32_t)(row * 128 + u * 16));
    }
    const __half* bSrc[4];
    uint32_t bDst[4];
#pragma unroll
    for (int i = 0; i < 4; i++) {
        int idx = i * 256 + tid;
        int n = idx >> 3, u = idx & 7;
        bSrc[i] = Bhi + (size_t)(blockN + n) * K + u * 8;
        bDst[i] = SWZ((uint32_t)(n * 128 + u * 16));
    }

    auto issue = [&](int c, int st) {
        const uint32_t sb = sb0 + st * STAGE_B;
#pragma unroll
        for (int i = 0; i < 4; i++)
            cp16(sb + aDst[i], aSrc[i] + c * 64);
#pragma unroll
        for (int i = 0; i < 4; i++)
            cp16(sb + 16384 + bDst[i], bSrc[i] + c * 64);
    };

    uint32_t oA[2], oB[4];
#pragma unroll
    for (int tm = 0; tm < 2; tm++)
        oA[tm] = (uint32_t)((wm * 32 + tm * 16 + (lane & 15)) * 128 + (lane >> 4) * 16);
#pragma unroll
    for (int g = 0; g < 4; g++)
        oB[g] = (uint32_t)((wn * 64 + g * 16 + (lane & 7) + ((lane >> 4) & 1) * 8) * 128
                           + ((lane >> 3) & 1) * 16);

    float Cr[2][8][4];
#pragma unroll
    for (int a = 0; a < 2; a++)
#pragma unroll
        for (int b = 0; b < 8; b++)
#pragma unroll
            for (int c = 0; c < 4; c++) Cr[a][b][c] = 0.f;

    issue(0, 0); cp_commit();
    if (NCH > 1) issue(1, 1);
    cp_commit();

    for (int c = 0; c < NCH; c++) {
        const int st = c % 3;
        cp_wait1();
        __syncthreads();
        if (c + 2 < NCH) { issue(c + 2, (c + 2) % 3); cp_commit(); }

        const uint32_t aB = sb0 + st * STAGE_B;
        const uint32_t bB = aB + 16384;
#pragma unroll
        for (int k16 = 0; k16 < 4; k16++) {
            const uint32_t ko = k16 * 32;
            uint32_t Ah[2][4], Bh[4][4];
#pragma unroll
            for (int tm = 0; tm < 2; tm++)
                ldm4(Ah[tm], aB + SWZ(oA[tm] + ko));
#pragma unroll
            for (int g = 0; g < 4; g++)
                ldm4(Bh[g], bB + SWZ(oB[g] + ko));
#pragma unroll
            for (int tm = 0; tm < 2; tm++)
#pragma unroll
                for (int tn = 0; tn < 8; tn++)
                    mma16816(Cr[tm][tn], Ah[tm],
                             Bh[tn >> 1][(tn & 1) * 2], Bh[tn >> 1][(tn & 1) * 2 + 1]);
        }
    }

    const int r0 = blockM + wm * 32 + (lane >> 2);
    const int n0 = blockN + wn * 64 + 2 * (lane & 3);
#pragma unroll
    for (int tm = 0; tm < 2; tm++) {
#pragma unroll
        for (int tn = 0; tn < 8; tn++) {
            int n = n0 + tn * 8;
            if (n >= NREAL) continue;
            float bx = bias[n], by = bias[n + 1];
#pragma unroll
            for (int half_ = 0; half_ < 2; half_++) {
                int m = r0 + tm * 16 + half_ * 8;
                float vx = Cr[tm][tn][half_ * 2 + 0] + bx;
                float vy = Cr[tm][tn][half_ * 2 + 1] + by;
                if (MODE == 1) {
                    size_t idx = (size_t)rowmap_of(m) * CC + n;
                    float2 a = *(const float2*)(aux + idx);
                    *(float2*)(g_xnew + idx) = make_float2(vx + a.x, vy + a.y);
                } else {
                    size_t idx = (size_t)m * CC + n;
                    float2 a = *(const float2*)(g_xnew + idx);
                    *(float2*)(outp + idx) = make_float2(vx + a.x, vy + a.y);
                }
            }
        }
    }
}

// ------------------------------ attention (HMMA) -----------------------------
// grid (NWIN, 3): one block per (window, head pair); q arrives pre-scaled.
__global__ __launch_bounds__(256)
void attn_kernel(const float* __restrict__ rpb) {
    __shared__ __align__(16) __half sq [2][64 * 40];
    __shared__ __align__(16) __half skk[2][64 * 40];
    __shared__ __align__(16) __half svt[2][32 * 72];
    __shared__ float srpb[2 * 169];
    __shared__ int   slabel[64];

    const int bwin = blockIdx.x;
    const int p    = blockIdx.y;
    const int tid  = threadIdx.x;
    const int lane = tid & 31;
    const int warp = tid >> 5;
    const int hw = warp >> 2;
    const int mb = warp & 3;

    for (int idx = tid; idx < 2 * 169; idx += 256)
        srpb[idx] = rpb[(idx % 169) * NH_ + p * 2 + idx / 169];
    if (tid < 64) {
        int label = 0;
        if (tid < NTOK) {
            int w = bwin & 63;
            int wh = w >> 3, ww = w & 7;
            int r = tid / WS_, c = tid - r * WS_;
            int gh = wh * WS_ + r, gw = ww * WS_ + c;
            int rr = (gh < HH - WS_) ? 0 : (gh < HH - SS_) ? 1 : 2;
            int cc = (gw < WW_ - WS_) ? 0 : (gw < WW_ - SS_) ? 1 : 2;
            label = rr * 3 + cc;
        }
        slabel[tid] = label;
    }
    for (int t = tid; t < (2 * 32 * 72) / 2; t += 256)
        ((uint32_t*)svt)[t] = 0;
    __syncthreads();

    // 16B-vector q/k/v loads: 392 items of (h, tok, u)
#pragma unroll
    for (int it = tid; it < 2 * NTOK * 4; it += 256) {
        int h = (it >= NTOK * 4);
        int rem = it - h * NTOK * 4;
        int tok = rem >> 2, u = rem & 3;
        const __half* src = g_qkv + (size_t)(bwin * NTOK + tok) * 576
                            + (p * 2 + h) * 32 + u * 8;
        uint4 qv = *(const uint4*)src;
        uint4 kv = *(const uint4*)(src + 192);
        uint4 vv = *(const uint4*)(src + 384);
        *(uint4*)(&sq[h][tok * 40 + u * 8])  = qv;
        *(uint4*)(&skk[h][tok * 40 + u * 8]) = kv;
        const __half* vh = (const __half*)&vv;
#pragma unroll
        for (int j = 0; j < 8; j++)
            svt[h][(u * 8 + j) * 72 + tok] = vh[j];
    }
    __syncthreads();

    const int head = p * 2 + hw;
    const float* rp = &srpb[hw * 169];
    const uint32_t qb = smem_u32(sq[hw]);
    const uint32_t kb = smem_u32(skk[hw]);
    const uint32_t vb = smem_u32(svt[hw]);

    const int i0 = mb * 16 + (lane >> 2);
    const int i1 = i0 + 8;
    const int ri0 = i0 / WS_, ci0 = i0 - ri0 * WS_;
    const int ri1 = i1 / WS_, ci1 = i1 - ri1 * WS_;

    float Cs[8][4];
#pragma unroll
    for (int f = 0; f < 8; f++)
#pragma unroll
        for (int s = 0; s < 4; s++) Cs[f][s] = 0.f;
#pragma unroll
    for (int k16 = 0; k16 < 2; k16++) {
        uint32_t Ah[4];
        ldm4(Ah, qb + ((mb * 16 + (lane & 15)) * 40 + (lane >> 4) * 8 + k16 * 16) * 2);
#pragma unroll
        for (int g = 0; g < 4; g++) {
            uint32_t Bf[4];
            ldm4(Bf, kb + ((g * 16 + (lane & 7) + ((lane >> 4) & 1) * 8) * 40
                           + ((lane >> 3) & 1) * 8 + k16 * 16) * 2);
            mma16816(Cs[g * 2 + 0], Ah, Bf[0], Bf[1]);
            mma16816(Cs[g * 2 + 1], Ah, Bf[2], Bf[3]);
        }
    }

    const int li0 = slabel[i0];
    const int li1 = slabel[i1];
#pragma unroll
    for (int f = 0; f < 8; f++) {
        int jb = f * 8 + (lane & 3) * 2;
#pragma unroll
        for (int s = 0; s < 2; s++) {
            int j = jb + s;
            if (j < NTOK) {
                int rj = j / WS_, cj = j - rj * WS_;
                int lj = slabel[j];
                if (i0 < NTOK) {
                    float b0 = rp[(ri0 - rj + 6) * 13 + (ci0 - cj + 6)];
                    Cs[f][s] += b0 - (li0 != lj ? 100.f : 0.f);
                } else Cs[f][s] = -1e30f;
                if (i1 < NTOK) {
                    float b1 = rp[(ri1 - rj + 6) * 13 + (ci1 - cj + 6)];
                    Cs[f][2 + s] += b1 - (li1 != lj ? 100.f : 0.f);
                } else Cs[f][2 + s] = -1e30f;
            } else {
                Cs[f][s] = -1e30f;
                Cs[f][2 + s] = -1e30f;
            }
        }
    }

    float mx0 = -1e30f, mx1 = -1e30f;
#pragma unroll
    for (int f = 0; f < 8; f++) {
        mx0 = fmaxf(mx0, fmaxf(Cs[f][0], Cs[f][1]));
        mx1 = fmaxf(mx1, fmaxf(Cs[f][2], Cs[f][3]));
    }
    mx0 = fmaxf(mx0, __shfl_xor_sync(0xffffffffu, mx0, 1));
    mx0 = fmaxf(mx0, __shfl_xor_sync(0xffffffffu, mx0, 2));
    mx1 = fmaxf(mx1, __shfl_xor_sync(0xffffffffu, mx1, 1));
    mx1 = fmaxf(mx1, __shfl_xor_sync(0xffffffffu, mx1, 2));
    float sum0 = 0.f, sum1 = 0.f;
#pragma unroll
    for (int f = 0; f < 8; f++) {
        Cs[f][0] = __expf(Cs[f][0] - mx0);
        Cs[f][1] = __expf(Cs[f][1] - mx0);
        Cs[f][2] = __expf(Cs[f][2] - mx1);
        Cs[f][3] = __expf(Cs[f][3] - mx1);
        sum0 += Cs[f][0] + Cs[f][1];
        sum1 += Cs[f][2] + Cs[f][3];
    }
    sum0 += __shfl_xor_sync(0xffffffffu, sum0, 1);
    sum0 += __shfl_xor_sync(0xffffffffu, sum0, 2);
    sum1 += __shfl_xor_sync(0xffffffffu, sum1, 1);
    sum1 += __shfl_xor_sync(0xffffffffu, sum1, 2);
    const float inv0 = 1.f / sum0;
    const float inv1 = 1.f / sum1;

    uint32_t Pa[4][4];
#pragma unroll
    for (int f2 = 0; f2 < 4; f2++) {
        Pa[f2][0] = h2u(__floats2half2_rn(Cs[2 * f2][0],     Cs[2 * f2][1]));
        Pa[f2][1] = h2u(__floats2half2_rn(Cs[2 * f2][2],     Cs[2 * f2][3]));
        Pa[f2][2] = h2u(__floats2half2_rn(Cs[2 * f2 + 1][0], Cs[2 * f2 + 1][1]));
        Pa[f2][3] = h2u(__floats2half2_rn(Cs[2 * f2 + 1][2], Cs[2 * f2 + 1][3]));
    }

    float Co[4][4];
#pragma unroll
    for (int f = 0; f < 4; f++)
#pragma unroll
        for (int s = 0; s < 4; s++) Co[f][s] = 0.f;
#pragma unroll
    for (int k16 = 0; k16 < 4; k16++) {
#pragma unroll
        for (int g = 0; g < 2; g++) {
            uint32_t Bv[4];
            ldm4(Bv, vb + ((g * 16 + (lane & 7) + ((lane >> 4) & 1) * 8) * 72
                           + ((lane >> 3) & 1) * 8 + k16 * 16) * 2);
            mma16816(Co[g * 2 + 0], Pa[k16], Bv[0], Bv[1]);
            mma16816(Co[g * 2 + 1], Pa[k16], Bv[2], Bv[3]);
        }
    }

#pragma unroll
    for (int f = 0; f < 4; f++) {
        int d = f * 8 + (lane & 3) * 2;
        if (i0 < NTOK)
            *(__half2*)(g_attn + (size_t)(bwin * NTOK + i0) * CC + head * 32 + d) =
                __floats2half2_rn(Co[f][0] * inv0, Co[f][1] * inv0);
        if (i1 < NTOK)
            *(__half2*)(g_attn + (size_t)(bwin * NTOK + i1) * CC + head * 32 + d) =
                __floats2half2_rn(Co[f][2] * inv1, Co[f][3] * inv1);
    }
}

// ------------------------------- launch -------------------------------------
extern "C" void kernel_launch(void* const* d_in, const int* in_sizes, int n_in,
                              void* d_out, int out_size) {
    const float* x       = (const float*)d_in[0];
    const float* norm1_w = (const float*)d_in[1];
    const float* norm1_b = (const float*)d_in[2];
    const float* qkv_w   = (const float*)d_in[3];
    const float* qkv_b   = (const float*)d_in[4];
    const float* rpb     = (const float*)d_in[5];
    const float* proj_w  = (const float*)d_in[6];
    const float* proj_b  = (const float*)d_in[7];
    const float* norm2_w = (const float*)d_in[8];
    const float* norm2_b = (const float*)d_in[9];
    const float* fc1_w   = (const float*)d_in[10];
    const float* fc1_b   = (const float*)d_in[11];
    const float* fc2_w   = (const float*)d_in[12];
    const float* fc2_b   = (const float*)d_in[13];
    float* out = (float*)d_out;

    __half *p_ln, *p_attn, *p_hid, *p_wqkv, *p_wproj, *p_wfc1, *p_wfc2;
    float *p_xnew;
    cudaGetSymbolAddress((void**)&p_ln,    g_ln);
    cudaGetSymbolAddress((void**)&p_attn,  g_attn);
    cudaGetSymbolAddress((void**)&p_hid,   g_hid);
    cudaGetSymbolAddress((void**)&p_xnew,  g_xnew);
    cudaGetSymbolAddress((void**)&p_wqkv,  g_wqkv);
    cudaGetSymbolAddress((void**)&p_wproj, g_wproj);
    cudaGetSymbolAddress((void**)&p_wfc1,  g_wfc1);
    cudaGetSymbolAddress((void**)&p_wfc2,  g_wfc2);

    const int BSM = 98304;
    cudaFuncSetAttribute(bres_gemm<0,576>, cudaFuncAttributeMaxDynamicSharedMemorySize, BSM);
    cudaFuncSetAttribute(bres_gemm<2,768>, cudaFuncAttributeMaxDynamicSharedMemorySize, BSM);
    cudaFuncSetAttribute(mma_gemm<192,1,192>, cudaFuncAttributeMaxDynamicSharedMemorySize, 3 * STAGE_B);
    cudaFuncSetAttribute(mma_gemm<768,3,192>, cudaFuncAttributeMaxDynamicSharedMemorySize, 3 * STAGE_B);

    whalf_all<<<2016, 256>>>(qkv_w, p_wqkv, proj_w, p_wproj,
                             fc1_w, p_wfc1, fc2_w, p_wfc2);                       // 0
    ln_kernel<<<MROWS / 8, 256>>>(x, norm1_w, norm1_b, p_ln);                     // 1
    bres_gemm<0,576><<<dim3(5, 392), 256, BSM>>>(p_ln, p_wqkv, qkv_b);            // 2
    attn_kernel<<<dim3(NWIN, 3), 256>>>(rpb);                                     // 3 (ncu)

    mma_gemm<192,1,192><<<dim3(2, 1568), 256, 3 * STAGE_B>>>(p_attn, p_wproj, proj_b, x, nullptr); // 4

    ln_kernel<<<MROWS / 8, 256>>>(p_xnew, norm2_w, norm2_b, p_ln);                // 5

    bres_gemm<2,768><<<dim3(6, 392), 256, BSM>>>(p_ln, p_wfc1, fc1_b);            // 6

    mma_gemm<768,3,192><<<dim3(2, 1568), 256, 3 * STAGE_B>>>(p_hid, p_wfc2, fc2_b, nullptr, out); // 7
}

// round 14
// speedup vs baseline: 1.1425x; 1.0418x over previous
#include <cuda_runtime.h>
#include <cuda_fp16.h>
#include <math.h>
#include <stdint.h>

// ---------------------------------------------------------------------------
// Swin block: fp16 HMMA GEMMs — B-resident (T=4) QKV/fc1, streaming proj/fc2;
// tensorized attention with precomputed bias+mask table; fp16 residual store.
// ---------------------------------------------------------------------------

#define BATCH   64
#define HH      56
#define WW_     56
#define CC      192
#define WS_     7
#define SS_     3
#define NH_     6
#define HD_     32
#define NTOK    49
#define NWIN    4096
#define MROWS   200704
#define HIDDEN  768
#define EPS_    1e-5f

// ------------------------------- scratch -----------------------------------
__device__ __half g_ln  [(size_t)MROWS * 192];
__device__ __half g_attn[(size_t)MROWS * 192];
__device__ __half g_hid [(size_t)MROWS * 768];
__device__ __half g_qkv [(size_t)MROWS * 576];
__device__ __half g_xnew[(size_t)MROWS * CC];     // fp16 residual stream
__device__ __half g_wqkv [640 * 192];
__device__ __half g_wproj[256 * 192];
__device__ __half g_wfc1 [768 * 192];
__device__ __half g_wfc2 [256 * 768];
// bias+mask table: [4 wtype][6 heads][49 rows][50 cols] fp16 (col 49 = -60000)
__device__ __align__(16) __half g_bias[4 * 6 * 49 * 50];

// ------------------------------ helpers -------------------------------------
__device__ __forceinline__ uint32_t smem_u32(const void* p) {
    uint32_t a;
    asm("{ .reg .u64 t; cvta.to.shared.u64 t, %1; cvt.u32.u64 %0, t; }"
        : "=r"(a) : "l"(p));
    return a;
}
#define SWZ(o) ((o) ^ (((o) >> 3) & 0x70))

__device__ __forceinline__ void cp16(uint32_t dst, const void* src) {
    asm volatile("cp.async.cg.shared.global [%0], [%1], 16;"
                 :: "r"(dst), "l"(src));
}
__device__ __forceinline__ void cp_commit() {
    asm volatile("cp.async.commit_group;" ::: "memory");
}
__device__ __forceinline__ void cp_wait1() {
    asm volatile("cp.async.wait_group 1;" ::: "memory");
}
__device__ __forceinline__ void ldm4(uint32_t* r, uint32_t addr) {
    asm volatile("ldmatrix.sync.aligned.m8n8.x4.shared.b16 {%0,%1,%2,%3}, [%4];"
                 : "=r"(r[0]), "=r"(r[1]), "=r"(r[2]), "=r"(r[3]) : "r"(addr));
}
__device__ __forceinline__ void mma16816(float* c, const uint32_t* a,
                                         uint32_t b0, uint32_t b1) {
    asm volatile(
        "mma.sync.aligned.m16n8k16.row.col.f32.f16.f16.f32 "
        "{%0,%1,%2,%3}, {%4,%5,%6,%7}, {%8,%9}, {%0,%1,%2,%3};"
        : "+f"(c[0]), "+f"(c[1]), "+f"(c[2]), "+f"(c[3])
        : "r"(a[0]), "r"(a[1]), "r"(a[2]), "r"(a[3]), "r"(b0), "r"(b1));
}
__device__ __forceinline__ uint32_t h2u(__half2 v) { return *(uint32_t*)&v; }

__device__ __forceinline__ int rowmap_of(int m) {
    int bwin = m / NTOK, tok = m - bwin * NTOK;
    int b = bwin >> 6, w = bwin & 63;
    int wh = w >> 3, ww = w & 7;
    int r = tok / WS_, c = tok - r * WS_;
    int oh = wh * WS_ + r + SS_; if (oh >= HH)  oh -= HH;
    int ow = ww * WS_ + c + SS_; if (ow >= WW_) ow -= WW_;
    return b * (HH * WW_) + oh * WW_ + ow;
}

// -------------------------- prep kernels ------------------------------------
// merged: 4 weight conversions + attention bias/mask table build
__global__ void whalf_all(const float* __restrict__ w0, __half* __restrict__ o0,
                          const float* __restrict__ w1, __half* __restrict__ o1,
                          const float* __restrict__ w2, __half* __restrict__ o2,
                          const float* __restrict__ w3, __half* __restrict__ o3,
                          const float* __restrict__ rpb) {
    int gidx = blockIdx.x * 256 + threadIdx.x;
    if (gidx < 516096) {
        const float* W; __half* out; int Kd, Nd, idx;
        if (gidx < 122880)      { W = w0; out = o0; Kd = 192; Nd = 576; idx = gidx; }
        else if (gidx < 172032) { W = w1; out = o1; Kd = 192; Nd = 192; idx = gidx - 122880; }
        else if (gidx < 319488) { W = w2; out = o2; Kd = 192; Nd = 768; idx = gidx - 172032; }
        else                    { W = w3; out = o3; Kd = 768; Nd = 192; idx = gidx - 319488; }
        int n = idx / Kd, k = idx - n * Kd;
        out[idx] = (n < Nd) ? __float2half(W[(size_t)k * Nd + n]) : __half(0);
    } else if (gidx < 573720) {
        // bias table main entries
        int t = gidx - 516096;
        int slab = t / 2401, e = t - slab * 2401;
        int i = e / 49, j = e - i * 49;
        int wtype = slab / 6, head = slab - wtype * 6;
        int hb = wtype >> 1, wb = wtype & 1;
        int ri = i / 7, ci = i - ri * 7;
        int rj = j / 7, cj = j - rj * 7;
        int li = (hb ? (ri < 4 ? 1 : 2) : 0) * 3 + (wb ? (ci < 4 ? 1 : 2) : 0);
        int lj = (hb ? (rj < 4 ? 1 : 2) : 0) * 3 + (wb ? (cj < 4 ? 1 : 2) : 0);
        float bias = rpb[((ri - rj + 6) * 13 + (ci - cj + 6)) * NH_ + head]
                     + (li != lj ? -100.f : 0.f);
        g_bias[slab * 2450 + i * 50 + j] = __float2half(bias);
    } else if (gidx < 574896) {
        // pad column j=49
        int t = gidx - 573720;
        int slab = t / 49, i = t - slab * 49;
        g_bias[slab * 2450 + i * 50 + 49] = __float2half(-60000.f);
    }
}

// LN: fp32 in -> fp16 out (LN1)
__global__ void ln_kernel(const float* __restrict__ in,
                          const float* __restrict__ w,
                          const float* __restrict__ b,
                          __half* __restrict__ out) {
    int row  = blockIdx.x * 8 + (threadIdx.x >> 5);
    int lane = threadIdx.x & 31;
    const float* p = in + (size_t)row * CC;
    float v[6];
    float s = 0.f;
#pragma unroll
    for (int i = 0; i < 6; i++) { v[i] = p[lane + 32 * i]; s += v[i]; }
#pragma unroll
    for (int o = 16; o > 0; o >>= 1) s += __shfl_xor_sync(0xffffffffu, s, o);
    float mean = s * (1.f / CC);
    float q = 0.f;
#pragma unroll
    for (int i = 0; i < 6; i++) { float d = v[i] - mean; q += d * d; }
#pragma unroll
    for (int o = 16; o > 0; o >>= 1) q += __shfl_xor_sync(0xffffffffu, q, o);
    float inv = rsqrtf(q * (1.f / CC) + EPS_);
    __half* op = out + (size_t)row * CC;
#pragma unroll
    for (int i = 0; i < 6; i++) {
        int c = lane + 32 * i;
        op[c] = __float2half((v[i] - mean) * inv * w[c] + b[c]);
    }
}

// LN: fp16 in -> fp16 out (LN2)
__global__ void ln16_kernel(const __half* __restrict__ in,
                            const float* __restrict__ w,
                            const float* __restrict__ b,
                            __half* __restrict__ out) {
    int row  = blockIdx.x * 8 + (threadIdx.x >> 5);
    int lane = threadIdx.x & 31;
    const __half2* p = (const __half2*)(in + (size_t)row * CC);
    float2 v[3];
    float s = 0.f;
#pragma unroll
    for (int i = 0; i < 3; i++) {
        v[i] = __half22float2(p[lane + 32 * i]);
        s += v[i].x + v[i].y;
    }
#pragma unroll
    for (int o = 16; o > 0; o >>= 1) s += __shfl_xor_sync(0xffffffffu, s, o);
    float mean = s * (1.f / CC);
    float q = 0.f;
#pragma unroll
    for (int i = 0; i < 3; i++) {
        float dx = v[i].x - mean, dy = v[i].y - mean;
        q += dx * dx + dy * dy;
    }
#pragma unroll
    for (int o = 16; o > 0; o >>= 1) q += __shfl_xor_sync(0xffffffffu, q, o);
    float inv = rsqrtf(q * (1.f / CC) + EPS_);
    __half2* op = (__half2*)(out + (size_t)row * CC);
#pragma unroll
    for (int i = 0; i < 3; i++) {
        int c = (lane + 32 * i) * 2;
        float y0 = (v[i].x - mean) * inv * w[c] + b[c];
        float y1 = (v[i].y - mean) * inv * w[c + 1] + b[c + 1];
        op[lane + 32 * i] = __floats2half2_rn(y0, y1);
    }
}

// ------------------- B-resident GEMM (K=192, T M-tiles/CTA) ------------------
#define TTILES 4
template<int MODE, int NREAL>
__global__ __launch_bounds__(256, 2)
void bres_gemm(const __half* __restrict__ A,
               const __half* __restrict__ Bhi,
               const float* __restrict__ bias)
{
    extern __shared__ __align__(128) char dynsm[];
    constexpr int K = 192;
    constexpr int NITER = 3 * TTILES;

    const int tid  = threadIdx.x;
    const int lane = tid & 31;
    const int warp = tid >> 5;
    const int wm = warp & 3;
    const int wn = warp >> 2;
    const int blockN  = blockIdx.x * 128;
    const int blockM0 = blockIdx.y * (TTILES * 128);
    const uint32_t sbB = smem_u32(dynsm);
    const uint32_t sbA = sbB + 49152;

#pragma unroll
    for (int i = 0; i < 12; i++) {
        int idx = i * 256 + tid;
        int chunk = idx >> 10, rem = idx & 1023;
        int n = rem >> 3, u = rem & 7;
        cp16(sbB + chunk * 16384 + SWZ((uint32_t)(n * 128 + u * 16)),
             Bhi + (size_t)(blockN + n) * K + chunk * 64 + u * 8);
    }

    int aRow[4];
    uint32_t aDst[4];
#pragma unroll
    for (int i = 0; i < 4; i++) {
        int idx = i * 256 + tid;
        aRow[i] = idx >> 3;
        int u = idx & 7;
        aDst[i] = SWZ((uint32_t)(aRow[i] * 128 + u * 16));
    }
    const int aCol = (tid & 7) * 8;

    auto issueA = [&](int tc) {
        int t = tc / 3, c = tc - t * 3;
        const uint32_t sb = sbA + (tc % 3) * 16384;
        int mbase = blockM0 + t * 128;
#pragma unroll
        for (int i = 0; i < 4; i++) {
            int m = mbase + aRow[i];
            int gm = (MODE == 0) ? rowmap_of(m) : m;
            cp16(sb + aDst[i], A + (size_t)gm * K + c * 64 + aCol);
        }
    };

    uint32_t oA[2], oB[4];
#pragma unroll
    for (int tm = 0; tm < 2; tm++)
        oA[tm] = (uint32_t)((wm * 32 + tm * 16 + (lane & 15)) * 128 + (lane >> 4) * 16);
#pragma unroll
    for (int g = 0; g < 4; g++)
        oB[g] = (uint32_t)((wn * 64 + g * 16 + (lane & 7) + ((lane >> 4) & 1) * 8) * 128
                           + ((lane >> 3) & 1) * 16);

    float Cr[2][8][4];
#pragma unroll
    for (int a = 0; a < 2; a++)
#pragma unroll
        for (int b = 0; b < 8; b++)
#pragma unroll
            for (int c = 0; c < 4; c++) Cr[a][b][c] = 0.f;

    issueA(0); cp_commit();
    issueA(1); cp_commit();

    const int r0l = wm * 32 + (lane >> 2);
    const int n0 = blockN + wn * 64 + 2 * (lane & 3);

    for (int tc = 0; tc < NITER; tc++) {
        const int c = tc % 3;
        cp_wait1();
        __syncthreads();
        if (tc + 2 < NITER) { issueA(tc + 2); cp_commit(); }

        const uint32_t aB = sbA + (tc % 3) * 16384;
        const uint32_t bB = sbB + c * 16384;
#pragma unroll
        for (int k16 = 0; k16 < 4; k16++) {
            const uint32_t ko = k16 * 32;
            uint32_t Ah[2][4], Bh[4][4];
#pragma unroll
            for (int tm = 0; tm < 2; tm++)
                ldm4(Ah[tm], aB + SWZ(oA[tm] + ko));
#pragma unroll
            for (int g = 0; g < 4; g++)
                ldm4(Bh[g], bB + SWZ(oB[g] + ko));
#pragma unroll
            for (int tm = 0; tm < 2; tm++)
#pragma unroll
                for (int tn = 0; tn < 8; tn++)
                    mma16816(Cr[tm][tn], Ah[tm],
                             Bh[tn >> 1][(tn & 1) * 2], Bh[tn >> 1][(tn & 1) * 2 + 1]);
        }

        if (c == 2) {
            const int mb = blockM0 + (tc / 3) * 128;
#pragma unroll
            for (int tm = 0; tm < 2; tm++) {
#pragma unroll
                for (int tn = 0; tn < 8; tn++) {
                    int n = n0 + tn * 8;
                    if (n >= NREAL) continue;
                    float bx = bias[n], by = bias[n + 1];
#pragma unroll
                    for (int half_ = 0; half_ < 2; half_++) {
                        int m = mb + r0l + tm * 16 + half_ * 8;
                        float vx = Cr[tm][tn][half_ * 2 + 0] + bx;
                        float vy = Cr[tm][tn][half_ * 2 + 1] + by;
                        if (MODE == 0) {
                            if (n < 192) {      // pre-scale q by 1/sqrt(32)
                                vx *= 0.17677669529663687f;
                                vy *= 0.17677669529663687f;
                            }
                            *(__half2*)(g_qkv + (size_t)m * 576 + n) =
                                __floats2half2_rn(vx, vy);
                        } else {
                            vx = 0.5f * vx * (1.f + erff(vx * 0.70710678118654752f));
                            vy = 0.5f * vy * (1.f + erff(vy * 0.70710678118654752f));
                            *(__half2*)(g_hid + (size_t)m * HIDDEN + n) =
                                __floats2half2_rn(vx, vy);
                        }
                    }
                }
            }
#pragma unroll
            for (int a = 0; a < 2; a++)
#pragma unroll
                for (int b = 0; b < 8; b++)
#pragma unroll
                    for (int cc2 = 0; cc2 < 4; cc2++) Cr[a][b][cc2] = 0.f;
        }
    }
}

// ----------------- streaming GEMM (proj MODE1, fc2 MODE3) --------------------
#define STAGE_B 32768
template<int K, int MODE, int NREAL>
__global__ __launch_bounds__(256, 2)
void mma_gemm(const __half* __restrict__ A,
              const __half* __restrict__ Bhi,
              const float* __restrict__ bias,
              const float* __restrict__ aux,
              float* __restrict__ outp)
{
    extern __shared__ __align__(128) char dynsm[];
    constexpr int NCH = K / 64;

    const int tid  = threadIdx.x;
    const int lane = tid & 31;
    const int warp = tid >> 5;
    const int wm = warp & 3;
    const int wn = warp >> 2;
    const int blockN = blockIdx.x * 128;
    const int blockM = blockIdx.y * 128;
    const uint32_t sb0 = smem_u32(dynsm);

    const __half* aSrc[4];
    uint32_t aDst[4];
#pragma unroll
    for (int i = 0; i < 4; i++) {
        int idx = i * 256 + tid;
        int row = idx >> 3, u = idx & 7;
        aSrc[i] = A + (size_t)(blockM + row) * K + u * 8;
        aDst[i] = SWZ((uint32_t)(row * 128 + u * 16));
    }
    const __half* bSrc[4];
    uint32_t bDst[4];
#pragma unroll
    for (int i = 0; i < 4; i++) {
        int idx = i * 256 + tid;
        int n = idx >> 3, u = idx & 7;
        bSrc[i] = Bhi + (size_t)(blockN + n) * K + u * 8;
        bDst[i] = SWZ((uint32_t)(n * 128 + u * 16));
    }

    auto issue = [&](int c, int st) {
        const uint32_t sb = sb0 + st * STAGE_B;
#pragma unroll
        for (int i = 0; i < 4; i++)
            cp16(sb + aDst[i], aSrc[i] + c * 64);
#pragma unroll
        for (int i = 0; i < 4; i++)
            cp16(sb + 16384 + bDst[i], bSrc[i] + c * 64);
    };

    uint32_t oA[2], oB[4];
#pragma unroll
    for (int tm = 0; tm < 2; tm++)
        oA[tm] = (uint32_t)((wm * 32 + tm * 16 + (lane & 15)) * 128 + (lane >> 4) * 16);
#pragma unroll
    for (int g = 0; g < 4; g++)
        oB[g] = (uint32_t)((wn * 64 + g * 16 + (lane & 7) + ((lane >> 4) & 1) * 8) * 128
                           + ((lane >> 3) & 1) * 16);

    float Cr[2][8][4];
#pragma unroll
    for (int a = 0; a < 2; a++)
#pragma unroll
        for (int b = 0; b < 8; b++)
#pragma unroll
            for (int c = 0; c < 4; c++) Cr[a][b][c] = 0.f;

    issue(0, 0); cp_commit();
    if (NCH > 1) issue(1, 1);
    cp_commit();

    for (int c = 0; c < NCH; c++) {
        const int st = c % 3;
        cp_wait1();
        __syncthreads();
        if (c + 2 < NCH) { issue(c + 2, (c + 2) % 3); cp_commit(); }

        const uint32_t aB = sb0 + st * STAGE_B;
        const uint32_t bB = aB + 16384;
#pragma unroll
        for (int k16 = 0; k16 < 4; k16++) {
            const uint32_t ko = k16 * 32;
            uint32_t Ah[2][4], Bh[4][4];
#pragma unroll
            for (int tm = 0; tm < 2; tm++)
                ldm4(Ah[tm], aB + SWZ(oA[tm] + ko));
#pragma unroll
            for (int g = 0; g < 4; g++)
                ldm4(Bh[g], bB + SWZ(oB[g] + ko));
#pragma unroll
            for (int tm = 0; tm < 2; tm++)
#pragma unroll
                for (int tn = 0; tn < 8; tn++)
                    mma16816(Cr[tm][tn], Ah[tm],
                             Bh[tn >> 1][(tn & 1) * 2], Bh[tn >> 1][(tn & 1) * 2 + 1]);
        }
    }

    const int r0 = blockM + wm * 32 + (lane >> 2);
    const int n0 = blockN + wn * 64 + 2 * (lane & 3);
#pragma unroll
    for (int tm = 0; tm < 2; tm++) {
#pragma unroll
        for (int tn = 0; tn < 8; tn++) {
            int n = n0 + tn * 8;
            if (n >= NREAL) continue;
            float bx = bias[n], by = bias[n + 1];
#pragma unroll
            for (int half_ = 0; half_ < 2; half_++) {
                int m = r0 + tm * 16 + half_ * 8;
                float vx = Cr[tm][tn][half_ * 2 + 0] + bx;
                float vy = Cr[tm][tn][half_ * 2 + 1] + by;
                if (MODE == 1) {
                    size_t idx = (size_t)rowmap_of(m) * CC + n;
                    float2 a = *(const float2*)(aux + idx);
                    *(__half2*)(g_xnew + idx) = __floats2half2_rn(vx + a.x, vy + a.y);
                } else {
                    size_t idx = (size_t)m * CC + n;
                    float2 a = __half22float2(*(const __half2*)(g_xnew + idx));
                    *(float2*)(outp + idx) = make_float2(vx + a.x, vy + a.y);
                }
            }
        }
    }
}

// ------------------------------ attention (HMMA) -----------------------------
// grid (NWIN, 3); bias+mask via precomputed g_bias table.
__global__ __launch_bounds__(256)
void attn_kernel() {
    __shared__ __align__(16) __half sq [2][64 * 40];
    __shared__ __align__(16) __half skk[2][64 * 40];
    __shared__ __align__(16) __half svt[2][32 * 72];

    const int bwin = blockIdx.x;
    const int p    = blockIdx.y;
    const int tid  = threadIdx.x;
    const int lane = tid & 31;
    const int warp = tid >> 5;
    const int hw = warp >> 2;
    const int mb = warp & 3;

    // zero v^T (all) + k pad rows 49..63 + q pad rows 49..63
    for (int t = tid; t < (2 * 32 * 72) / 2; t += 256)
        ((uint32_t*)svt)[t] = 0;
    for (int t = tid; t < 2 * 15 * 20; t += 256) {   // 15 rows x 40 halves = 20 uint32/row? (40h=80B=20u32)
        int h = t / 300, r = t - h * 300;
        ((uint32_t*)(&skk[h][49 * 40]))[r] = 0;
        ((uint32_t*)(&sq [h][49 * 40]))[r] = 0;
    }
    __syncthreads();

    // 16B-vector q/k/v loads
#pragma unroll
    for (int it = tid; it < 2 * NTOK * 4; it += 256) {
        int h = (it >= NTOK * 4);
        int rem = it - h * NTOK * 4;
        int tok = rem >> 2, u = rem & 3;
        const __half* src = g_qkv + (size_t)(bwin * NTOK + tok) * 576
                            + (p * 2 + h) * 32 + u * 8;
        uint4 qv = *(const uint4*)src;
        uint4 kv = *(const uint4*)(src + 192);
        uint4 vv = *(const uint4*)(src + 384);
        *(uint4*)(&sq[h][tok * 40 + u * 8])  = qv;
        *(uint4*)(&skk[h][tok * 40 + u * 8]) = kv;
        const __half* vh = (const __half*)&vv;
#pragma unroll
        for (int j = 0; j < 8; j++)
            svt[h][(u * 8 + j) * 72 + tok] = vh[j];
    }
    __syncthreads();

    const int head = p * 2 + hw;
    const int w = bwin & 63;
    const int wtype = (((w >> 3) == 7) ? 2 : 0) | (((w & 7) == 7) ? 1 : 0);
    const __half* tbl = g_bias + (wtype * 6 + head) * 2450;
    const uint32_t qb = smem_u32(sq[hw]);
    const uint32_t kb = smem_u32(skk[hw]);
    const uint32_t vb = smem_u32(svt[hw]);

    const int i0 = mb * 16 + (lane >> 2);
    const int i1 = i0 + 8;
    const bool v0 = (i0 < NTOK), v1 = (i1 < NTOK);

    float Cs[8][4];
#pragma unroll
    for (int f = 0; f < 8; f++)
#pragma unroll
        for (int s = 0; s < 4; s++) Cs[f][s] = 0.f;
#pragma unroll
    for (int k16 = 0; k16 < 2; k16++) {
        uint32_t Ah[4];
        ldm4(Ah, qb + ((mb * 16 + (lane & 15)) * 40 + (lane >> 4) * 8 + k16 * 16) * 2);
#pragma unroll
        for (int g = 0; g < 4; g++) {
            uint32_t Bf[4];
            ldm4(Bf, kb + ((g * 16 + (lane & 7) + ((lane >> 4) & 1) * 8) * 40
                           + ((lane >> 3) & 1) * 8 + k16 * 16) * 2);
            mma16816(Cs[g * 2 + 0], Ah, Bf[0], Bf[1]);
            mma16816(Cs[g * 2 + 1], Ah, Bf[2], Bf[3]);
        }
    }

    // ---- bias + mask from table ----
    const int q2 = (lane & 3) * 2;
    const __half* t0 = tbl + i0 * 50;
    const __half* t1 = tbl + i1 * 50;
#pragma unroll
    for (int f = 0; f < 8; f++) {
        int jb = f * 8 + q2;
        if (jb <= 48) {
            if (v0) {
                float2 b = __half22float2(*(const __half2*)(t0 + jb));
                Cs[f][0] += b.x; Cs[f][1] += b.y;
            } else { Cs[f][0] = Cs[f][1] = -60000.f; }
            if (v1) {
                float2 b = __half22float2(*(const __half2*)(t1 + jb));
                Cs[f][2] += b.x; Cs[f][3] += b.y;
            } else { Cs[f][2] = Cs[f][3] = -60000.f; }
        } else {
            Cs[f][0] = Cs[f][1] = Cs[f][2] = Cs[f][3] = -60000.f;
        }
    }

    float mx0 = -1e30f, mx1 = -1e30f;
#pragma unroll
    for (int f = 0; f < 8; f++) {
        mx0 = fmaxf(mx0, fmaxf(Cs[f][0], Cs[f][1]));
        mx1 = fmaxf(mx1, fmaxf(Cs[f][2], Cs[f][3]));
    }
    mx0 = fmaxf(mx0, __shfl_xor_sync(0xffffffffu, mx0, 1));
    mx0 = fmaxf(mx0, __shfl_xor_sync(0xffffffffu, mx0, 2));
    mx1 = fmaxf(mx1, __shfl_xor_sync(0xffffffffu, mx1, 1));
    mx1 = fmaxf(mx1, __shfl_xor_sync(0xffffffffu, mx1, 2));
    float sum0 = 0.f, sum1 = 0.f;
#pragma unroll
    for (int f = 0; f < 8; f++) {
        Cs[f][0] = __expf(Cs[f][0] - mx0);
        Cs[f][1] = __expf(Cs[f][1] - mx0);
        Cs[f][2] = __expf(Cs[f][2] - mx1);
        Cs[f][3] = __expf(Cs[f][3] - mx1);
        sum0 += Cs[f][0] + Cs[f][1];
        sum1 += Cs[f][2] + Cs[f][3];
    }
    sum0 += __shfl_xor_sync(0xffffffffu, sum0, 1);
    sum0 += __shfl_xor_sync(0xffffffffu, sum0, 2);
    sum1 += __shfl_xor_sync(0xffffffffu, sum1, 1);
    sum1 += __shfl_xor_sync(0xffffffffu, sum1, 2);
    const float inv0 = 1.f / sum0;
    const float inv1 = 1.f / sum1;

    uint32_t Pa[4][4];
#pragma unroll
    for (int f2 = 0; f2 < 4; f2++) {
        Pa[f2][0] = h2u(__floats2half2_rn(Cs[2 * f2][0],     Cs[2 * f2][1]));
        Pa[f2][1] = h2u(__floats2half2_rn(Cs[2 * f2][2],     Cs[2 * f2][3]));
        Pa[f2][2] = h2u(__floats2half2_rn(Cs[2 * f2 + 1][0], Cs[2 * f2 + 1][1]));
        Pa[f2][3] = h2u(__floats2half2_rn(Cs[2 * f2 + 1][2], Cs[2 * f2 + 1][3]));
    }

    float Co[4][4];
#pragma unroll
    for (int f = 0; f < 4; f++)
#pragma unroll
        for (int s = 0; s < 4; s++) Co[f][s] = 0.f;
#pragma unroll
    for (int k16 = 0; k16 < 4; k16++) {
#pragma unroll
        for (int g = 0; g < 2; g++) {
            uint32_t Bv[4];
            ldm4(Bv, vb + ((g * 16 + (lane & 7) + ((lane >> 4) & 1) * 8) * 72
                           + ((lane >> 3) & 1) * 8 + k16 * 16) * 2);
            mma16816(Co[g * 2 + 0], Pa[k16], Bv[0], Bv[1]);
            mma16816(Co[g * 2 + 1], Pa[k16], Bv[2], Bv[3]);
        }
    }

#pragma unroll
    for (int f = 0; f < 4; f++) {
        int d = f * 8 + (lane & 3) * 2;
        if (v0)
            *(__half2*)(g_attn + (size_t)(bwin * NTOK + i0) * CC + head * 32 + d) =
                __floats2half2_rn(Co[f][0] * inv0, Co[f][1] * inv0);
        if (v1)
            *(__half2*)(g_attn + (size_t)(bwin * NTOK + i1) * CC + head * 32 + d) =
                __floats2half2_rn(Co[f][2] * inv1, Co[f][3] * inv1);
    }
}

// ------------------------------- launch -------------------------------------
extern "C" void kernel_launch(void* const* d_in, const int* in_sizes, int n_in,
                              void* d_out, int out_size) {
    const float* x       = (const float*)d_in[0];
    const float* norm1_w = (const float*)d_in[1];
    const float* norm1_b = (const float*)d_in[2];
    const float* qkv_w   = (const float*)d_in[3];
    const float* qkv_b   = (const float*)d_in[4];
    const float* rpb     = (const float*)d_in[5];
    const float* proj_w  = (const float*)d_in[6];
    const float* proj_b  = (const float*)d_in[7];
    const float* norm2_w = (const float*)d_in[8];
    const float* norm2_b = (const float*)d_in[9];
    const float* fc1_w   = (const float*)d_in[10];
    const float* fc1_b   = (const float*)d_in[11];
    const float* fc2_w   = (const float*)d_in[12];
    const float* fc2_b   = (const float*)d_in[13];
    float* out = (float*)d_out;

    __half *p_ln, *p_attn, *p_hid, *p_xnew, *p_wqkv, *p_wproj, *p_wfc1, *p_wfc2;
    cudaGetSymbolAddress((void**)&p_ln,    g_ln);
    cudaGetSymbolAddress((void**)&p_attn,  g_attn);
    cudaGetSymbolAddress((void**)&p_hid,   g_hid);
    cudaGetSymbolAddress((void**)&p_xnew,  g_xnew);
    cudaGetSymbolAddress((void**)&p_wqkv,  g_wqkv);
    cudaGetSymbolAddress((void**)&p_wproj, g_wproj);
    cudaGetSymbolAddress((void**)&p_wfc1,  g_wfc1);
    cudaGetSymbolAddress((void**)&p_wfc2,  g_wfc2);

    const int BSM = 98304;
    cudaFuncSetAttribute(bres_gemm<0,576>, cudaFuncAttributeMaxDynamicSharedMemorySize, BSM);
    cudaFuncSetAttribute(bres_gemm<2,768>, cudaFuncAttributeMaxDynamicSharedMemorySize, BSM);
    cudaFuncSetAttribute(mma_gemm<192,1,192>, cudaFuncAttributeMaxDynamicSharedMemorySize, 3 * STAGE_B);
    cudaFuncSetAttribute(mma_gemm<768,3,192>, cudaFuncAttributeMaxDynamicSharedMemorySize, 3 * STAGE_B);

    whalf_all<<<2246, 256>>>(qkv_w, p_wqkv, proj_w, p_wproj,
                             fc1_w, p_wfc1, fc2_w, p_wfc2, rpb);                  // 0
    ln_kernel<<<MROWS / 8, 256>>>(x, norm1_w, norm1_b, p_ln);                     // 1
    bres_gemm<0,576><<<dim3(5, 392), 256, BSM>>>(p_ln, p_wqkv, qkv_b);            // 2
    attn_kernel<<<dim3(NWIN, 3), 256>>>();                                        // 3 (ncu)

    mma_gemm<192,1,192><<<dim3(2, 1568), 256, 3 * STAGE_B>>>(p_attn, p_wproj, proj_b, x, nullptr); // 4

    ln16_kernel<<<MROWS / 8, 256>>>(p_xnew, norm2_w, norm2_b, p_ln);              // 5

    bres_gemm<2,768><<<dim3(6, 392), 256, BSM>>>(p_ln, p_wfc1, fc1_b);            // 6

    mma_gemm<768,3,192><<<dim3(2, 1568), 256, 3 * STAGE_B>>>(p_hid, p_wfc2, fc2_b, nullptr, out); // 7
}

// round 15
// speedup vs baseline: 1.2459x; 1.0905x over previous
#include <cuda_runtime.h>
#include <cuda_fp16.h>
#include <math.h>
#include <stdint.h>

// ---------------------------------------------------------------------------
// Swin block: fp16 HMMA GEMMs with BN=96 (zero N-padding) — B-resident (T=4)
// QKV/fc1, streaming proj/fc2; tensorized attention w/ bias table.
// ---------------------------------------------------------------------------

#define BATCH   64
#define HH      56
#define WW_     56
#define CC      192
#define WS_     7
#define SS_     3
#define NH_     6
#define HD_     32
#define NTOK    49
#define NWIN    4096
#define MROWS   200704
#define HIDDEN  768
#define EPS_    1e-5f

// ------------------------------- scratch -----------------------------------
__device__ __half g_ln  [(size_t)MROWS * 192];
__device__ __half g_attn[(size_t)MROWS * 192];
__device__ __half g_hid [(size_t)MROWS * 768];
__device__ __half g_qkv [(size_t)MROWS * 576];
__device__ __half g_xnew[(size_t)MROWS * CC];
__device__ __half g_wqkv [576 * 192];
__device__ __half g_wproj[192 * 192];
__device__ __half g_wfc1 [768 * 192];
__device__ __half g_wfc2 [192 * 768];
__device__ __align__(16) __half g_bias[4 * 6 * 49 * 50];

// ------------------------------ helpers -------------------------------------
__device__ __forceinline__ uint32_t smem_u32(const void* p) {
    uint32_t a;
    asm("{ .reg .u64 t; cvta.to.shared.u64 t, %1; cvt.u32.u64 %0, t; }"
        : "=r"(a) : "l"(p));
    return a;
}
#define SWZ(o) ((o) ^ (((o) >> 3) & 0x70))

__device__ __forceinline__ void cp16(uint32_t dst, const void* src) {
    asm volatile("cp.async.cg.shared.global [%0], [%1], 16;"
                 :: "r"(dst), "l"(src));
}
__device__ __forceinline__ void cp_commit() {
    asm volatile("cp.async.commit_group;" ::: "memory");
}
__device__ __forceinline__ void cp_wait1() {
    asm volatile("cp.async.wait_group 1;" ::: "memory");
}
__device__ __forceinline__ void ldm4(uint32_t* r, uint32_t addr) {
    asm volatile("ldmatrix.sync.aligned.m8n8.x4.shared.b16 {%0,%1,%2,%3}, [%4];"
                 : "=r"(r[0]), "=r"(r[1]), "=r"(r[2]), "=r"(r[3]) : "r"(addr));
}
__device__ __forceinline__ void mma16816(float* c, const uint32_t* a,
                                         uint32_t b0, uint32_t b1) {
    asm volatile(
        "mma.sync.aligned.m16n8k16.row.col.f32.f16.f16.f32 "
        "{%0,%1,%2,%3}, {%4,%5,%6,%7}, {%8,%9}, {%0,%1,%2,%3};"
        : "+f"(c[0]), "+f"(c[1]), "+f"(c[2]), "+f"(c[3])
        : "r"(a[0]), "r"(a[1]), "r"(a[2]), "r"(a[3]), "r"(b0), "r"(b1));
}
__device__ __forceinline__ uint32_t h2u(__half2 v) { return *(uint32_t*)&v; }

__device__ __forceinline__ int rowmap_of(int m) {
    int bwin = m / NTOK, tok = m - bwin * NTOK;
    int b = bwin >> 6, w = bwin & 63;
    int wh = w >> 3, ww = w & 7;
    int r = tok / WS_, c = tok - r * WS_;
    int oh = wh * WS_ + r + SS_; if (oh >= HH)  oh -= HH;
    int ow = ww * WS_ + c + SS_; if (ow >= WW_) ow -= WW_;
    return b * (HH * WW_) + oh * WW_ + ow;
}

// -------------------------- prep kernels ------------------------------------
// merged: 4 weight conversions (no padding) + bias/mask table build
__global__ void whalf_all(const float* __restrict__ w0, __half* __restrict__ o0,
                          const float* __restrict__ w1, __half* __restrict__ o1,
                          const float* __restrict__ w2, __half* __restrict__ o2,
                          const float* __restrict__ w3, __half* __restrict__ o3,
                          const float* __restrict__ rpb) {
    int gidx = blockIdx.x * 256 + threadIdx.x;
    if (gidx < 442368) {
        const float* W; __half* out; int Kd, Nd, idx;
        if (gidx < 110592)      { W = w0; out = o0; Kd = 192; Nd = 576; idx = gidx; }
        else if (gidx < 147456) { W = w1; out = o1; Kd = 192; Nd = 192; idx = gidx - 110592; }
        else if (gidx < 294912) { W = w2; out = o2; Kd = 192; Nd = 768; idx = gidx - 147456; }
        else                    { W = w3; out = o3; Kd = 768; Nd = 192; idx = gidx - 294912; }
        int n = idx / Kd, k = idx - n * Kd;
        out[idx] = __float2half(W[(size_t)k * Nd + n]);
    } else if (gidx < 499992) {
        int t = gidx - 442368;
        int slab = t / 2401, e = t - slab * 2401;
        int i = e / 49, j = e - i * 49;
        int wtype = slab / 6, head = slab - wtype * 6;
        int hb = wtype >> 1, wb = wtype & 1;
        int ri = i / 7, ci = i - ri * 7;
        int rj = j / 7, cj = j - rj * 7;
        int li = (hb ? (ri < 4 ? 1 : 2) : 0) * 3 + (wb ? (ci < 4 ? 1 : 2) : 0);
        int lj = (hb ? (rj < 4 ? 1 : 2) : 0) * 3 + (wb ? (cj < 4 ? 1 : 2) : 0);
        float bias = rpb[((ri - rj + 6) * 13 + (ci - cj + 6)) * NH_ + head]
                     + (li != lj ? -100.f : 0.f);
        g_bias[slab * 2450 + i * 50 + j] = __float2half(bias);
    } else if (gidx < 501168) {
        int t = gidx - 499992;
        int slab = t / 49, i = t - slab * 49;
        g_bias[slab * 2450 + i * 50 + 49] = __float2half(-60000.f);
    }
}

__global__ void ln_kernel(const float* __restrict__ in,
                          const float* __restrict__ w,
                          const float* __restrict__ b,
                          __half* __restrict__ out) {
    int row  = blockIdx.x * 8 + (threadIdx.x >> 5);
    int lane = threadIdx.x & 31;
    const float* p = in + (size_t)row * CC;
    float v[6];
    float s = 0.f;
#pragma unroll
    for (int i = 0; i < 6; i++) { v[i] = p[lane + 32 * i]; s += v[i]; }
#pragma unroll
    for (int o = 16; o > 0; o >>= 1) s += __shfl_xor_sync(0xffffffffu, s, o);
    float mean = s * (1.f / CC);
    float q = 0.f;
#pragma unroll
    for (int i = 0; i < 6; i++) { float d = v[i] - mean; q += d * d; }
#pragma unroll
    for (int o = 16; o > 0; o >>= 1) q += __shfl_xor_sync(0xffffffffu, q, o);
    float inv = rsqrtf(q * (1.f / CC) + EPS_);
    __half* op = out + (size_t)row * CC;
#pragma unroll
    for (int i = 0; i < 6; i++) {
        int c = lane + 32 * i;
        op[c] = __float2half((v[i] - mean) * inv * w[c] + b[c]);
    }
}

__global__ void ln16_kernel(const __half* __restrict__ in,
                            const float* __restrict__ w,
                            const float* __restrict__ b,
                            __half* __restrict__ out) {
    int row  = blockIdx.x * 8 + (threadIdx.x >> 5);
    int lane = threadIdx.x & 31;
    const __half2* p = (const __half2*)(in + (size_t)row * CC);
    float2 v[3];
    float s = 0.f;
#pragma unroll
    for (int i = 0; i < 3; i++) {
        v[i] = __half22float2(p[lane + 32 * i]);
        s += v[i].x + v[i].y;
    }
#pragma unroll
    for (int o = 16; o > 0; o >>= 1) s += __shfl_xor_sync(0xffffffffu, s, o);
    float mean = s * (1.f / CC);
    float q = 0.f;
#pragma unroll
    for (int i = 0; i < 3; i++) {
        float dx = v[i].x - mean, dy = v[i].y - mean;
        q += dx * dx + dy * dy;
    }
#pragma unroll
    for (int o = 16; o > 0; o >>= 1) q += __shfl_xor_sync(0xffffffffu, q, o);
    float inv = rsqrtf(q * (1.f / CC) + EPS_);
    __half2* op = (__half2*)(out + (size_t)row * CC);
#pragma unroll
    for (int i = 0; i < 3; i++) {
        int c = (lane + 32 * i) * 2;
        float y0 = (v[i].x - mean) * inv * w[c] + b[c];
        float y1 = (v[i].y - mean) * inv * w[c + 1] + b[c + 1];
        op[lane + 32 * i] = __floats2half2_rn(y0, y1);
    }
}

// ------------------- B-resident GEMM (K=192, BN=96, T M-tiles) ---------------
// smem: B 3 chunks x 12KB (36864) | A 3 stages x 16KB (49152) = 86016
#define TTILES 4
#define BRES_SMEM 86016
template<int MODE>
__global__ __launch_bounds__(256, 2)
void bres_gemm(const __half* __restrict__ A,
               const __half* __restrict__ Bhi,
               const float* __restrict__ bias)
{
    extern __shared__ __align__(128) char dynsm[];
    constexpr int K = 192;
    constexpr int NITER = 3 * TTILES;

    const int tid  = threadIdx.x;
    const int lane = tid & 31;
    const int warp = tid >> 5;
    const int wm = warp & 3;
    const int wn = warp >> 2;
    const int blockN  = blockIdx.x * 96;
    const int blockM0 = blockIdx.y * (TTILES * 128);
    const uint32_t sbB = smem_u32(dynsm);
    const uint32_t sbA = sbB + 36864;

    // B once: 3 chunks x 96 rows x 8 cp16 = 2304 -> 9/thread
#pragma unroll
    for (int i = 0; i < 9; i++) {
        int idx = i * 256 + tid;
        int chunk = idx / 768, rem = idx - chunk * 768;
        int n = rem >> 3, u = rem & 7;
        cp16(sbB + chunk * 12288 + SWZ((uint32_t)(n * 128 + u * 16)),
             Bhi + (size_t)(blockN + n) * K + chunk * 64 + u * 8);
    }

    int aRow[4];
    uint32_t aDst[4];
#pragma unroll
    for (int i = 0; i < 4; i++) {
        int idx = i * 256 + tid;
        aRow[i] = idx >> 3;
        int u = idx & 7;
        aDst[i] = SWZ((uint32_t)(aRow[i] * 128 + u * 16));
    }
    const int aCol = (tid & 7) * 8;

    auto issueA = [&](int tc) {
        int t = tc / 3, c = tc - t * 3;
        const uint32_t sb = sbA + (tc % 3) * 16384;
        int mbase = blockM0 + t * 128;
#pragma unroll
        for (int i = 0; i < 4; i++) {
            int m = mbase + aRow[i];
            int gm = (MODE == 0) ? rowmap_of(m) : m;
            cp16(sb + aDst[i], A + (size_t)gm * K + c * 64 + aCol);
        }
    };

    uint32_t oA[2], oB[3];
#pragma unroll
    for (int tm = 0; tm < 2; tm++)
        oA[tm] = (uint32_t)((wm * 32 + tm * 16 + (lane & 15)) * 128 + (lane >> 4) * 16);
#pragma unroll
    for (int g = 0; g < 3; g++)
        oB[g] = (uint32_t)((wn * 48 + g * 16 + (lane & 7) + ((lane >> 4) & 1) * 8) * 128
                           + ((lane >> 3) & 1) * 16);

    float Cr[2][6][4];
#pragma unroll
    for (int a = 0; a < 2; a++)
#pragma unroll
        for (int b = 0; b < 6; b++)
#pragma unroll
            for (int c = 0; c < 4; c++) Cr[a][b][c] = 0.f;

    issueA(0); cp_commit();
    issueA(1); cp_commit();

    const int r0l = wm * 32 + (lane >> 2);
    const int n0 = blockN + wn * 48 + 2 * (lane & 3);

    for (int tc = 0; tc < NITER; tc++) {
        const int c = tc % 3;
        cp_wait1();
        __syncthreads();
        if (tc + 2 < NITER) { issueA(tc + 2); cp_commit(); }

        const uint32_t aB = sbA + (tc % 3) * 16384;
        const uint32_t bB = sbB + c * 12288;
#pragma unroll
        for (int k16 = 0; k16 < 4; k16++) {
            const uint32_t ko = k16 * 32;
            uint32_t Ah[2][4], Bh[3][4];
#pragma unroll
            for (int tm = 0; tm < 2; tm++)
                ldm4(Ah[tm], aB + SWZ(oA[tm] + ko));
#pragma unroll
            for (int g = 0; g < 3; g++)
                ldm4(Bh[g], bB + SWZ(oB[g] + ko));
#pragma unroll
            for (int tm = 0; tm < 2; tm++)
#pragma unroll
                for (int tn = 0; tn < 6; tn++)
                    mma16816(Cr[tm][tn], Ah[tm],
                             Bh[tn >> 1][(tn & 1) * 2], Bh[tn >> 1][(tn & 1) * 2 + 1]);
        }

        if (c == 2) {
            const int mb = blockM0 + (tc / 3) * 128;
#pragma unroll
            for (int tm = 0; tm < 2; tm++) {
#pragma unroll
                for (int tn = 0; tn < 6; tn++) {
                    int n = n0 + tn * 8;
                    float bx = bias[n], by = bias[n + 1];
#pragma unroll
                    for (int half_ = 0; half_ < 2; half_++) {
                        int m = mb + r0l + tm * 16 + half_ * 8;
                        float vx = Cr[tm][tn][half_ * 2 + 0] + bx;
                        float vy = Cr[tm][tn][half_ * 2 + 1] + by;
                        if (MODE == 0) {
                            if (n < 192) {
                                vx *= 0.17677669529663687f;
                                vy *= 0.17677669529663687f;
                            }
                            *(__half2*)(g_qkv + (size_t)m * 576 + n) =
                                __floats2half2_rn(vx, vy);
                        } else {
                            vx = 0.5f * vx * (1.f + erff(vx * 0.70710678118654752f));
                            vy = 0.5f * vy * (1.f + erff(vy * 0.70710678118654752f));
                            *(__half2*)(g_hid + (size_t)m * HIDDEN + n) =
                                __floats2half2_rn(vx, vy);
                        }
                    }
                }
            }
#pragma unroll
            for (int a = 0; a < 2; a++)
#pragma unroll
                for (int b = 0; b < 6; b++)
#pragma unroll
                    for (int cc2 = 0; cc2 < 4; cc2++) Cr[a][b][cc2] = 0.f;
        }
    }
}

// ----------------- streaming GEMM (proj MODE1, fc2 MODE3), BN=96 -------------
// stage: A 16KB | B 12KB = 28672; 3 stages = 86016
#define STAGE_B 28672
template<int K, int MODE>
__global__ __launch_bounds__(256, 2)
void mma_gemm(const __half* __restrict__ A,
              const __half* __restrict__ Bhi,
              const float* __restrict__ bias,
              const float* __restrict__ aux,
              float* __restrict__ outp)
{
    extern __shared__ __align__(128) char dynsm[];
    constexpr int NCH = K / 64;

    const int tid  = threadIdx.x;
    const int lane = tid & 31;
    const int warp = tid >> 5;
    const int wm = warp & 3;
    const int wn = warp >> 2;
    const int blockN = blockIdx.x * 96;
    const int blockM = blockIdx.y * 128;
    const uint32_t sb0 = smem_u32(dynsm);

    const __half* aSrc[4];
    uint32_t aDst[4];
#pragma unroll
    for (int i = 0; i < 4; i++) {
        int idx = i * 256 + tid;
        int row = idx >> 3, u = idx & 7;
        aSrc[i] = A + (size_t)(blockM + row) * K + u * 8;
        aDst[i] = SWZ((uint32_t)(row * 128 + u * 16));
    }
    const __half* bSrc[3];
    uint32_t bDst[3];
#pragma unroll
    for (int i = 0; i < 3; i++) {
        int idx = i * 256 + tid;
        int n = idx >> 3, u = idx & 7;
        bSrc[i] = Bhi + (size_t)(blockN + n) * K + u * 8;
        bDst[i] = SWZ((uint32_t)(n * 128 + u * 16));
    }

    auto issue = [&](int c, int st) {
        const uint32_t sb = sb0 + st * STAGE_B;
#pragma unroll
        for (int i = 0; i < 4; i++)
            cp16(sb + aDst[i], aSrc[i] + c * 64);
#pragma unroll
        for (int i = 0; i < 3; i++)
            cp16(sb + 16384 + bDst[i], bSrc[i] + c * 64);
    };

    uint32_t oA[2], oB[3];
#pragma unroll
    for (int tm = 0; tm < 2; tm++)
        oA[tm] = (uint32_t)((wm * 32 + tm * 16 + (lane & 15)) * 128 + (lane >> 4) * 16);
#pragma unroll
    for (int g = 0; g < 3; g++)
        oB[g] = (uint32_t)((wn * 48 + g * 16 + (lane & 7) + ((lane >> 4) & 1) * 8) * 128
                           + ((lane >> 3) & 1) * 16);

    float Cr[2][6][4];
#pragma unroll
    for (int a = 0; a < 2; a++)
#pragma unroll
        for (int b = 0; b < 6; b++)
#pragma unroll
            for (int c = 0; c < 4; c++) Cr[a][b][c] = 0.f;

    issue(0, 0); cp_commit();
    if (NCH > 1) issue(1, 1);
    cp_commit();

    for (int c = 0; c < NCH; c++) {
        const int st = c % 3;
        cp_wait1();
        __syncthreads();
        if (c + 2 < NCH) { issue(c + 2, (c + 2) % 3); cp_commit(); }

        const uint32_t aB = sb0 + st * STAGE_B;
        const uint32_t bB = aB + 16384;
#pragma unroll
        for (int k16 = 0; k16 < 4; k16++) {
            const uint32_t ko = k16 * 32;
            uint32_t Ah[2][4], Bh[3][4];
#pragma unroll
            for (int tm = 0; tm < 2; tm++)
                ldm4(Ah[tm], aB + SWZ(oA[tm] + ko));
#pragma unroll
            for (int g = 0; g < 3; g++)
                ldm4(Bh[g], bB + SWZ(oB[g] + ko));
#pragma unroll
            for (int tm = 0; tm < 2; tm++)
#pragma unroll
                for (int tn = 0; tn < 6; tn++)
                    mma16816(Cr[tm][tn], Ah[tm],
                             Bh[tn >> 1][(tn & 1) * 2], Bh[tn >> 1][(tn & 1) * 2 + 1]);
        }
    }

    const int r0 = blockM + wm * 32 + (lane >> 2);
    const int n0 = blockN + wn * 48 + 2 * (lane & 3);
#pragma unroll
    for (int tm = 0; tm < 2; tm++) {
#pragma unroll
        for (int tn = 0; tn < 6; tn++) {
            int n = n0 + tn * 8;
            float bx = bias[n], by = bias[n + 1];
#pragma unroll
            for (int half_ = 0; half_ < 2; half_++) {
                int m = r0 + tm * 16 + half_ * 8;
                float vx = Cr[tm][tn][half_ * 2 + 0] + bx;
                float vy = Cr[tm][tn][half_ * 2 + 1] + by;
                if (MODE == 1) {
                    size_t idx = (size_t)rowmap_of(m) * CC + n;
                    float2 a = *(const float2*)(aux + idx);
                    *(__half2*)(g_xnew + idx) = __floats2half2_rn(vx + a.x, vy + a.y);
                } else {
                    size_t idx = (size_t)m * CC + n;
                    float2 a = __half22float2(*(const __half2*)(g_xnew + idx));
                    *(float2*)(outp + idx) = make_float2(vx + a.x, vy + a.y);
                }
            }
        }
    }
}

// ------------------------------ attention (HMMA) -----------------------------
__global__ __launch_bounds__(256)
void attn_kernel() {
    __shared__ __align__(16) __half sq [2][64 * 40];
    __shared__ __align__(16) __half skk[2][64 * 40];
    __shared__ __align__(16) __half svt[2][32 * 72];

    const int bwin = blockIdx.x;
    const int p    = blockIdx.y;
    const int tid  = threadIdx.x;
    const int lane = tid & 31;
    const int warp = tid >> 5;
    const int hw = warp >> 2;
    const int mb = warp & 3;

    for (int t = tid; t < (2 * 32 * 72) / 2; t += 256)
        ((uint32_t*)svt)[t] = 0;
    for (int t = tid; t < 2 * 15 * 20; t += 256) {
        int h = t / 300, r = t - h * 300;
        ((uint32_t*)(&skk[h][49 * 40]))[r] = 0;
        ((uint32_t*)(&sq [h][49 * 40]))[r] = 0;
    }
    __syncthreads();

#pragma unroll
    for (int it = tid; it < 2 * NTOK * 4; it += 256) {
        int h = (it >= NTOK * 4);
        int rem = it - h * NTOK * 4;
        int tok = rem >> 2, u = rem & 3;
        const __half* src = g_qkv + (size_t)(bwin * NTOK + tok) * 576
                            + (p * 2 + h) * 32 + u * 8;
        uint4 qv = *(const uint4*)src;
        uint4 kv = *(const uint4*)(src + 192);
        uint4 vv = *(const uint4*)(src + 384);
        *(uint4*)(&sq[h][tok * 40 + u * 8])  = qv;
        *(uint4*)(&skk[h][tok * 40 + u * 8]) = kv;
        const __half* vh = (const __half*)&vv;
#pragma unroll
        for (int j = 0; j < 8; j++)
            svt[h][(u * 8 + j) * 72 + tok] = vh[j];
    }
    __syncthreads();

    const int head = p * 2 + hw;
    const int w = bwin & 63;
    const int wtype = (((w >> 3) == 7) ? 2 : 0) | (((w & 7) == 7) ? 1 : 0);
    const __half* tbl = g_bias + (wtype * 6 + head) * 2450;
    const uint32_t qb = smem_u32(sq[hw]);
    const uint32_t kb = smem_u32(skk[hw]);
    const uint32_t vb = smem_u32(svt[hw]);

    const int i0 = mb * 16 + (lane >> 2);
    const int i1 = i0 + 8;
    const bool v0 = (i0 < NTOK), v1 = (i1 < NTOK);

    float Cs[8][4];
#pragma unroll
    for (int f = 0; f < 8; f++)
#pragma unroll
        for (int s = 0; s < 4; s++) Cs[f][s] = 0.f;
#pragma unroll
    for (int k16 = 0; k16 < 2; k16++) {
        uint32_t Ah[4];
        ldm4(Ah, qb + ((mb * 16 + (lane & 15)) * 40 + (lane >> 4) * 8 + k16 * 16) * 2);
#pragma unroll
        for (int g = 0; g < 4; g++) {
            uint32_t Bf[4];
            ldm4(Bf, kb + ((g * 16 + (lane & 7) + ((lane >> 4) & 1) * 8) * 40
                           + ((lane >> 3) & 1) * 8 + k16 * 16) * 2);
            mma16816(Cs[g * 2 + 0], Ah, Bf[0], Bf[1]);
            mma16816(Cs[g * 2 + 1], Ah, Bf[2], Bf[3]);
        }
    }

    const int q2 = (lane & 3) * 2;
    const __half* t0 = tbl + i0 * 50;
    const __half* t1 = tbl + i1 * 50;
#pragma unroll
    for (int f = 0; f < 8; f++) {
        int jb = f * 8 + q2;
        if (jb <= 48) {
            if (v0) {
                float2 b = __half22float2(*(const __half2*)(t0 + jb));
                Cs[f][0] += b.x; Cs[f][1] += b.y;
            } else { Cs[f][0] = Cs[f][1] = -60000.f; }
            if (v1) {
                float2 b = __half22float2(*(const __half2*)(t1 + jb));
                Cs[f][2] += b.x; Cs[f][3] += b.y;
            } else { Cs[f][2] = Cs[f][3] = -60000.f; }
        } else {
            Cs[f][0] = Cs[f][1] = Cs[f][2] = Cs[f][3] = -60000.f;
        }
    }

    float mx0 = -1e30f, mx1 = -1e30f;
#pragma unroll
    for (int f = 0; f < 8; f++) {
        mx0 = fmaxf(mx0, fmaxf(Cs[f][0], Cs[f][1]));
        mx1 = fmaxf(mx1, fmaxf(Cs[f][2], Cs[f][3]));
    }
    mx0 = fmaxf(mx0, __shfl_xor_sync(0xffffffffu, mx0, 1));
    mx0 = fmaxf(mx0, __shfl_xor_sync(0xffffffffu, mx0, 2));
    mx1 = fmaxf(mx1, __shfl_xor_sync(0xffffffffu, mx1, 1));
    mx1 = fmaxf(mx1, __shfl_xor_sync(0xffffffffu, mx1, 2));
    float sum0 = 0.f, sum1 = 0.f;
#pragma unroll
    for (int f = 0; f < 8; f++) {
        Cs[f][0] = __expf(Cs[f][0] - mx0);
        Cs[f][1] = __expf(Cs[f][1] - mx0);
        Cs[f][2] = __expf(Cs[f][2] - mx1);
        Cs[f][3] = __expf(Cs[f][3] - mx1);
        sum0 += Cs[f][0] + Cs[f][1];
        sum1 += Cs[f][2] + Cs[f][3];
    }
    sum0 += __shfl_xor_sync(0xffffffffu, sum0, 1);
    sum0 += __shfl_xor_sync(0xffffffffu, sum0, 2);
    sum1 += __shfl_xor_sync(0xffffffffu, sum1, 1);
    sum1 += __shfl_xor_sync(0xffffffffu, sum1, 2);
    const float inv0 = 1.f / sum0;
    const float inv1 = 1.f / sum1;

    uint32_t Pa[4][4];
#pragma unroll
    for (int f2 = 0; f2 < 4; f2++) {
        Pa[f2][0] = h2u(__floats2half2_rn(Cs[2 * f2][0],     Cs[2 * f2][1]));
        Pa[f2][1] = h2u(__floats2half2_rn(Cs[2 * f2][2],     Cs[2 * f2][3]));
        Pa[f2][2] = h2u(__floats2half2_rn(Cs[2 * f2 + 1][0], Cs[2 * f2 + 1][1]));
        Pa[f2][3] = h2u(__floats2half2_rn(Cs[2 * f2 + 1][2], Cs[2 * f2 + 1][3]));
    }

    float Co[4][4];
#pragma unroll
    for (int f = 0; f < 4; f++)
#pragma unroll
        for (int s = 0; s < 4; s++) Co[f][s] = 0.f;
#pragma unroll
    for (int k16 = 0; k16 < 4; k16++) {
#pragma unroll
        for (int g = 0; g < 2; g++) {
            uint32_t Bv[4];
            ldm4(Bv, vb + ((g * 16 + (lane & 7) + ((lane >> 4) & 1) * 8) * 72
                           + ((lane >> 3) & 1) * 8 + k16 * 16) * 2);
            mma16816(Co[g * 2 + 0], Pa[k16], Bv[0], Bv[1]);
            mma16816(Co[g * 2 + 1], Pa[k16], Bv[2], Bv[3]);
        }
    }

#pragma unroll
    for (int f = 0; f < 4; f++) {
        int d = f * 8 + (lane & 3) * 2;
        if (v0)
            *(__half2*)(g_attn + (size_t)(bwin * NTOK + i0) * CC + head * 32 + d) =
                __floats2half2_rn(Co[f][0] * inv0, Co[f][1] * inv0);
        if (v1)
            *(__half2*)(g_attn + (size_t)(bwin * NTOK + i1) * CC + head * 32 + d) =
                __floats2half2_rn(Co[f][2] * inv1, Co[f][3] * inv1);
    }
}

// ------------------------------- launch -------------------------------------
extern "C" void kernel_launch(void* const* d_in, const int* in_sizes, int n_in,
                              void* d_out, int out_size) {
    const float* x       = (const float*)d_in[0];
    const float* norm1_w = (const float*)d_in[1];
    const float* norm1_b = (const float*)d_in[2];
    const float* qkv_w   = (const float*)d_in[3];
    const float* qkv_b   = (const float*)d_in[4];
    const float* rpb     = (const float*)d_in[5];
    const float* proj_w  = (const float*)d_in[6];
    const float* proj_b  = (const float*)d_in[7];
    const float* norm2_w = (const float*)d_in[8];
    const float* norm2_b = (const float*)d_in[9];
    const float* fc1_w   = (const float*)d_in[10];
    const float* fc1_b   = (const float*)d_in[11];
    const float* fc2_w   = (const float*)d_in[12];
    const float* fc2_b   = (const float*)d_in[13];
    float* out = (float*)d_out;

    __half *p_ln, *p_attn, *p_hid, *p_xnew, *p_wqkv, *p_wproj, *p_wfc1, *p_wfc2;
    cudaGetSymbolAddress((void**)&p_ln,    g_ln);
    cudaGetSymbolAddress((void**)&p_attn,  g_attn);
    cudaGetSymbolAddress((void**)&p_hid,   g_hid);
    cudaGetSymbolAddress((void**)&p_xnew,  g_xnew);
    cudaGetSymbolAddress((void**)&p_wqkv,  g_wqkv);
    cudaGetSymbolAddress((void**)&p_wproj, g_wproj);
    cudaGetSymbolAddress((void**)&p_wfc1,  g_wfc1);
    cudaGetSymbolAddress((void**)&p_wfc2,  g_wfc2);

    cudaFuncSetAttribute(bres_gemm<0>, cudaFuncAttributeMaxDynamicSharedMemorySize, BRES_SMEM);
    cudaFuncSetAttribute(bres_gemm<2>, cudaFuncAttributeMaxDynamicSharedMemorySize, BRES_SMEM);
    cudaFuncSetAttribute(mma_gemm<192,1>, cudaFuncAttributeMaxDynamicSharedMemorySize, 3 * STAGE_B);
    cudaFuncSetAttribute(mma_gemm<768,3>, cudaFuncAttributeMaxDynamicSharedMemorySize, 3 * STAGE_B);

    whalf_all<<<1958, 256>>>(qkv_w, p_wqkv, proj_w, p_wproj,
                             fc1_w, p_wfc1, fc2_w, p_wfc2, rpb);                  // 0
    ln_kernel<<<MROWS / 8, 256>>>(x, norm1_w, norm1_b, p_ln);                     // 1
    bres_gemm<0><<<dim3(6, 392), 256, BRES_SMEM>>>(p_ln, p_wqkv, qkv_b);          // 2
    attn_kernel<<<dim3(NWIN, 3), 256>>>();                                        // 3 (ncu)

    mma_gemm<192,1><<<dim3(2, 1568), 256, 3 * STAGE_B>>>(p_attn, p_wproj, proj_b, x, nullptr); // 4

    ln16_kernel<<<MROWS / 8, 256>>>(p_xnew, norm2_w, norm2_b, p_ln);              // 5

    bres_gemm<2><<<dim3(8, 392), 256, BRES_SMEM>>>(p_ln, p_wfc1, fc1_b);          // 6

    mma_gemm<768,3><<<dim3(2, 1568), 256, 3 * STAGE_B>>>(p_hid, p_wfc2, fc2_b, nullptr, out); // 7
}